// round 3
// baseline (speedup 1.0000x reference)
#include <cuda_runtime.h>

// MultiHeadAttention: B=2, S=2048, D=1024, H=16, dh=64, fp32.
// Round 2: same fp32 SIMT baseline as R1 (untested due to infra failure),
// hardened: kernels use __device__ scratch globals directly (no
// cudaGetSymbolAddress in kernel_launch).
//   1) gemm_nt_k  (128x128x16 tile, NT, bias, fused head-split epilogues) x4
//   2) attn_k     (flash-style online softmax, 64-row q tiles)

#define DM 1024
#define NH 16
#define HD 64
#define BB 2
#define SS 2048
#define NTOK (BB * SS)

__device__ float g_QT[BB * NH * HD * SS]; // [b][h][d][s]
__device__ float g_KT[BB * NH * HD * SS]; // [b][h][d][s]
__device__ float g_V [BB * NH * SS * HD]; // [b][h][s][d]
__device__ float g_A [NTOK * DM];         // [n][e] attention output

// C[m, e] = sum_d A[m,d] * W[e,d] + bias[e]
// mode 0: C flat [m][e] (C = dst)
// mode 1: head-split   [b][h][s][d] (dst = g_V)
// mode 2: head-split-T [b][h][d][s] (dst = g_QT or g_KT via dst ptr)
__global__ __launch_bounds__(256) void gemm_nt_k(
    const float* __restrict__ A, const float* __restrict__ W,
    const float* __restrict__ bias, float* __restrict__ C, int mode)
{
    __shared__ float As[16][132];
    __shared__ float Ws[16][132];
    const int tid = threadIdx.x;
    const int tx = tid & 15, ty = tid >> 4;
    const int m0 = blockIdx.y * 128, n0 = blockIdx.x * 128;

    float acc[8][8] = {};

    for (int kt = 0; kt < DM; kt += 16) {
#pragma unroll
        for (int i = 0; i < 2; i++) {
            int f = tid + i * 256;
            int row = f >> 2, kq = (f & 3) << 2;
            float4 va = *(const float4*)&A[(size_t)(m0 + row) * DM + kt + kq];
            As[kq + 0][row] = va.x; As[kq + 1][row] = va.y;
            As[kq + 2][row] = va.z; As[kq + 3][row] = va.w;
            float4 vw = *(const float4*)&W[(size_t)(n0 + row) * DM + kt + kq];
            Ws[kq + 0][row] = vw.x; Ws[kq + 1][row] = vw.y;
            Ws[kq + 2][row] = vw.z; Ws[kq + 3][row] = vw.w;
        }
        __syncthreads();
#pragma unroll
        for (int k = 0; k < 16; k++) {
            float a[8], b[8];
            *(float4*)&a[0] = *(const float4*)&As[k][ty * 8];
            *(float4*)&a[4] = *(const float4*)&As[k][ty * 8 + 4];
            *(float4*)&b[0] = *(const float4*)&Ws[k][tx * 8];
            *(float4*)&b[4] = *(const float4*)&Ws[k][tx * 8 + 4];
#pragma unroll
            for (int i = 0; i < 8; i++)
#pragma unroll
                for (int j = 0; j < 8; j++)
                    acc[i][j] = fmaf(a[i], b[j], acc[i][j]);
        }
        __syncthreads();
    }

#pragma unroll
    for (int i = 0; i < 8; i++) {
        int m = m0 + ty * 8 + i;
        int bb = m >> 11;           // m / SS
        int sIdx = m & (SS - 1);    // m % SS
#pragma unroll
        for (int j = 0; j < 8; j++) {
            int e = n0 + tx * 8 + j;
            float v = acc[i][j] + bias[e];
            if (mode == 0) {
                C[(size_t)m * DM + e] = v;
            } else {
                int h = e >> 6, d = e & 63;
                if (mode == 1)
                    g_V[(((size_t)(bb * NH + h)) * SS + sIdx) * HD + d] = v;
                else
                    C[(((size_t)(bb * NH + h)) * HD + d) * SS + sIdx] = v;
            }
        }
    }
}

// Flash-style attention. Grid: (SS/64, BB*NH), 256 threads.
// Q/K stored head-transposed [d][s] so smem k-major tiles load clean.
__global__ __launch_bounds__(256) void attn_k(const int* __restrict__ mask)
{
    extern __shared__ float sm[];
    float* Qs = sm;               // [64][68]  Qs[k][r]
    float* Ks = Qs + 64 * 68;     // [64][68]  Ks[k][c]
    float* Ps = Ks + 64 * 68;     // [64][68]  Ps[c][r]
    float* Vs = Ps + 64 * 68;     // [64][64]  Vs[j][d]

    const int tid = threadIdx.x;
    const int tx = tid & 15, ty = tid >> 4;
    const int bh = blockIdx.y;
    const int b = bh >> 4, h = bh & 15;
    const int q0 = blockIdx.x * 64;

    const float* Qh = g_QT + (size_t)bh * HD * SS;
    const float* Kh = g_KT + (size_t)bh * HD * SS;
    const float* Vh = g_V  + (size_t)bh * SS * HD;
    const int* mrow = mask + (size_t)b * SS * SS;

#pragma unroll
    for (int i = 0; i < 4; i++) {
        int f = tid + i * 256;
        int k = f >> 4, rq = (f & 15) << 2;
        *(float4*)&Qs[k * 68 + rq] = *(const float4*)&Qh[(size_t)k * SS + q0 + rq];
    }

    float o[4][4] = {};
    float mr[4], lr[4];
#pragma unroll
    for (int i = 0; i < 4; i++) { mr[i] = -1e30f; lr[i] = 0.f; }
    __syncthreads();

    for (int kv0 = 0; kv0 < SS; kv0 += 64) {
#pragma unroll
        for (int i = 0; i < 4; i++) {
            int f = tid + i * 256;
            int k = f >> 4, cq = (f & 15) << 2;
            *(float4*)&Ks[k * 68 + cq] = *(const float4*)&Kh[(size_t)k * SS + kv0 + cq];
            *(float4*)&Vs[k * 64 + cq] = *(const float4*)&Vh[(size_t)(kv0 + k) * HD + cq];
        }
        __syncthreads();

        // S = Q K^T (64x64 tile, 4x4 per thread)
        float s[4][4] = {};
#pragma unroll 8
        for (int k = 0; k < 64; k++) {
            float a[4], c[4];
            *(float4*)a = *(const float4*)&Qs[k * 68 + ty * 4];
            *(float4*)c = *(const float4*)&Ks[k * 68 + tx * 4];
#pragma unroll
            for (int i = 0; i < 4; i++)
#pragma unroll
                for (int j = 0; j < 4; j++)
                    s[i][j] = fmaf(a[i], c[j], s[i][j]);
        }

        // scale + mask
#pragma unroll
        for (int i = 0; i < 4; i++) {
            int q = q0 + ty * 4 + i;
            int4 mm = *(const int4*)&mrow[(size_t)q * SS + kv0 + tx * 4];
            s[i][0] = mm.x ? s[i][0] * 0.125f : -1e9f;
            s[i][1] = mm.y ? s[i][1] * 0.125f : -1e9f;
            s[i][2] = mm.z ? s[i][2] * 0.125f : -1e9f;
            s[i][3] = mm.w ? s[i][3] * 0.125f : -1e9f;
        }

        // online softmax (16 lanes of a half-warp share row group ty)
#pragma unroll
        for (int i = 0; i < 4; i++) {
            float mx = fmaxf(fmaxf(s[i][0], s[i][1]), fmaxf(s[i][2], s[i][3]));
#pragma unroll
            for (int off = 8; off; off >>= 1)
                mx = fmaxf(mx, __shfl_xor_sync(0xffffffffu, mx, off));
            float mn = fmaxf(mr[i], mx);
            float corr = __expf(mr[i] - mn);
            float ls = 0.f;
#pragma unroll
            for (int j = 0; j < 4; j++) { s[i][j] = __expf(s[i][j] - mn); ls += s[i][j]; }
#pragma unroll
            for (int off = 8; off; off >>= 1)
                ls += __shfl_xor_sync(0xffffffffu, ls, off);
            lr[i] = lr[i] * corr + ls;
            mr[i] = mn;
#pragma unroll
            for (int j = 0; j < 4; j++) o[i][j] *= corr;
        }

        // stage P into smem transposed: Ps[c][r]
#pragma unroll
        for (int jj = 0; jj < 4; jj++) {
            float4 pv = make_float4(s[0][jj], s[1][jj], s[2][jj], s[3][jj]);
            *(float4*)&Ps[(tx * 4 + jj) * 68 + ty * 4] = pv;
        }
        __syncthreads();

        // O += P V
#pragma unroll 8
        for (int j = 0; j < 64; j++) {
            float a[4], vv[4];
            *(float4*)a = *(const float4*)&Ps[j * 68 + ty * 4];
            *(float4*)vv = *(const float4*)&Vs[j * 64 + tx * 4];
#pragma unroll
            for (int i = 0; i < 4; i++)
#pragma unroll
                for (int d = 0; d < 4; d++)
                    o[i][d] = fmaf(a[i], vv[d], o[i][d]);
        }
        __syncthreads();
    }

#pragma unroll
    for (int i = 0; i < 4; i++) {
        float inv = 1.f / lr[i];
        int q = q0 + ty * 4 + i;
        float4 outv = make_float4(o[i][0] * inv, o[i][1] * inv,
                                  o[i][2] * inv, o[i][3] * inv);
        *(float4*)&g_A[((size_t)(b * SS + q)) * DM + h * HD + tx * 4] = outv;
    }
}

static const int ATTN_SMEM = (3 * 64 * 68 + 64 * 64) * (int)sizeof(float); // 68608

extern "C" void kernel_launch(void* const* d_in, const int* in_sizes, int n_in,
                              void* d_out, int out_size)
{
    const float* Xq  = (const float*)d_in[0];
    const float* Xkv = (const float*)d_in[1];
    const int*   msk = (const int*)d_in[2];
    const float* Wq  = (const float*)d_in[3];
    const float* bq  = (const float*)d_in[4];
    const float* Wk  = (const float*)d_in[5];
    const float* bk  = (const float*)d_in[6];
    const float* Wv  = (const float*)d_in[7];
    const float* bv  = (const float*)d_in[8];
    const float* Wo  = (const float*)d_in[9];
    const float* bo  = (const float*)d_in[10];
    float* out = (float*)d_out;

    cudaFuncSetAttribute(attn_k, cudaFuncAttributeMaxDynamicSharedMemorySize, ATTN_SMEM);

    // device-side symbol addresses resolved at compile time inside kernels;
    // for mode-2 GEMMs we still need a dst pointer choice, so use a tiny
    // selector: pass nullptr-distinguished dst via C arg.
    float* qt;  cudaGetSymbolAddress((void**)&qt,  g_QT);
    float* ktp; cudaGetSymbolAddress((void**)&ktp, g_KT);
    float* ab;  cudaGetSymbolAddress((void**)&ab,  g_A);

    dim3 gg(DM / 128, NTOK / 128), gb(256);
    gemm_nt_k<<<gg, gb>>>(Xq,  Wq, bq, qt,  2);  // Q -> [b][h][d][s]
    gemm_nt_k<<<gg, gb>>>(Xkv, Wk, bk, ktp, 2);  // K -> [b][h][d][s]
    gemm_nt_k<<<gg, gb>>>(Xkv, Wv, bv, nullptr, 1); // V -> g_V [b][h][s][d]
    attn_k<<<dim3(SS / 64, BB * NH), 256, ATTN_SMEM>>>(msk);
    gemm_nt_k<<<gg, gb>>>(ab, Wo, bo, out, 0);   // output projection
}

// round 6
// speedup vs baseline: 1.4879x; 1.4879x over previous
#include <cuda_runtime.h>
#include <cuda_bf16.h>
#include <cstdint>

// MultiHeadAttention: B=2, S=2048, D=1024, H=16, dh=64, fp32.
// R6: harness PTX targets plain sm_103 (no tcgen05). Use fallback tensor path:
//   mma.sync.aligned.m16n8k16 bf16 (HMMA) + ldmatrix, hi/lo split x3 for
//   fp32-class accuracy, for all 4 projection GEMMs.
// SIMT flash attention unchanged from the 1993us baseline (943us measured).

#define DM 1024
#define NH 16
#define HD 64
#define BB 2
#define SS 2048
#define NTOK (BB * SS)

// ---------------- scratch (no allocation allowed) ----------------
__device__ float g_QT[BB*NH*HD*SS];   // [b][h][d][s]
__device__ float g_KT[BB*NH*HD*SS];   // [b][h][d][s]
__device__ float g_V [NTOK*DM];       // flat [tok][e]
__device__ float g_A [NTOK*DM];       // flat [tok][e]
__device__ __nv_bfloat16 g_Xq_h[NTOK*DM], g_Xq_l[NTOK*DM];
__device__ __nv_bfloat16 g_Xk_h[NTOK*DM], g_Xk_l[NTOK*DM];
__device__ __nv_bfloat16 g_W_h[4*DM*DM], g_W_l[4*DM*DM];
__device__ __nv_bfloat16 g_A_h[NTOK*DM], g_A_l[NTOK*DM];

__device__ __forceinline__ uint32_t smem_u32(const void* p) {
    uint32_t a;
    asm("{ .reg .u64 t; cvta.to.shared.u64 t, %1; cvt.u32.u64 %0, t; }" : "=r"(a) : "l"(p));
    return a;
}
__device__ __forceinline__ void ldmx4(uint32_t* r, uint32_t addr) {
    asm volatile("ldmatrix.sync.aligned.m8n8.x4.shared.b16 {%0,%1,%2,%3}, [%4];"
                 : "=r"(r[0]), "=r"(r[1]), "=r"(r[2]), "=r"(r[3]) : "r"(addr));
}
__device__ __forceinline__ void mma16816(float* c, const uint32_t* a, const uint32_t* b) {
    asm volatile(
        "mma.sync.aligned.m16n8k16.row.col.f32.bf16.bf16.f32 "
        "{%0,%1,%2,%3}, {%4,%5,%6,%7}, {%8,%9}, {%0,%1,%2,%3};"
        : "+f"(c[0]), "+f"(c[1]), "+f"(c[2]), "+f"(c[3])
        : "r"(a[0]), "r"(a[1]), "r"(a[2]), "r"(a[3]), "r"(b[0]), "r"(b[1]));
}

// ---------------- fp32 -> bf16 hi/lo split ----------------
__global__ __launch_bounds__(256) void split_k(
    const float* __restrict__ src, __nv_bfloat16* __restrict__ hi,
    __nv_bfloat16* __restrict__ lo, int n4)
{
    int i = blockIdx.x * blockDim.x + threadIdx.x;
    if (i >= n4) return;
    float4 v = ((const float4*)src)[i];
    float x[4] = {v.x, v.y, v.z, v.w};
    __nv_bfloat16 h[4], l[4];
#pragma unroll
    for (int q = 0; q < 4; q++) {
        h[q] = __float2bfloat16_rn(x[q]);
        l[q] = __float2bfloat16_rn(x[q] - __bfloat162float(h[q]));
    }
    __nv_bfloat162* H = (__nv_bfloat162*)(hi + (size_t)i * 4);
    __nv_bfloat162* L = (__nv_bfloat162*)(lo + (size_t)i * 4);
    H[0] = __halves2bfloat162(h[0], h[1]);
    H[1] = __halves2bfloat162(h[2], h[3]);
    L[0] = __halves2bfloat162(l[0], l[1]);
    L[1] = __halves2bfloat162(l[2], l[3]);
}

// ---------------- HMMA GEMM: C[m,e] = sum_d A[m,d] W[e,d] + bias[e] ----------------
// 128x128 CTA tile, K chunks of 64. 8 warps: wm = wid&3 (m), wn = wid>>2 (n).
// Warp tile 32(m) x 64(n). 3 passes: Ah*Bh + Al*Bh + Ah*Bl.
// mode 0: C flat [m][e];  mode 2: head-split-T [b][h][d][s]
__global__ __launch_bounds__(256, 2) void gemm_tc(
    const __nv_bfloat16* __restrict__ Ah, const __nv_bfloat16* __restrict__ Al,
    const __nv_bfloat16* __restrict__ Bh, const __nv_bfloat16* __restrict__ Bl,
    const float* __restrict__ bias, float* __restrict__ C, int mode)
{
    extern __shared__ char smem[];
    const uint32_t sb = smem_u32(smem);
    // tile offsets: Ah 0, Al 16K, Bh 32K, Bl 48K; each [128 rows][128B], swizzled
    const int tid = threadIdx.x, lane = tid & 31, wid = tid >> 5;
    const int wm = wid & 3, wn = wid >> 2;
    const int m0 = blockIdx.y * 128, n0 = blockIdx.x * 128;

    float acc[2][8][4] = {};

    // gmem->smem loader mapping: each thread copies one (row, 64B-half) per tensor
    const int lrow = tid >> 1, lhalf = tid & 1;
    const size_t arow = (size_t)(m0 + lrow) * DM + lhalf * 32;
    const size_t brow = (size_t)(n0 + lrow) * DM + lhalf * 32;
    uint32_t so[4];
#pragma unroll
    for (int q = 0; q < 4; q++)
        so[q] = lrow * 128 + ((((lhalf * 4 + q) ^ (lrow & 7)) & 7) << 4);

    // ldmatrix lane address components
    // A (16x16 row-major): tiles (r0-7,k0)(r8-15,k0)(r0-7,k8)(r8-15,k8)
    const int a_rp = (lane & 7) + ((lane >> 3) & 1) * 8;  // row within atom
    const int a_up = (lane >> 4);                          // +unit (k8)
    // B (8n x 16k as two n-atoms): tiles (n0-7,k0)(n0-7,k8)(n8-15,k0)(n8-15,k8)
    const int b_rp = (lane & 7) + ((lane >> 4) << 3);
    const int b_up = (lane >> 3) & 1;

    for (int c = 0; c < 16; c++) {
        const int kt = c * 64;
        if (c) __syncthreads();   // tiles free to overwrite
        {
            const uint4* pAH = (const uint4*)(Ah + arow + kt);
            const uint4* pAL = (const uint4*)(Al + arow + kt);
            const uint4* pBH = (const uint4*)(Bh + brow + kt);
            const uint4* pBL = (const uint4*)(Bl + brow + kt);
#pragma unroll
            for (int q = 0; q < 4; q++) {
                *(uint4*)(smem + so[q])         = pAH[q];
                *(uint4*)(smem + 16384 + so[q]) = pAL[q];
                *(uint4*)(smem + 32768 + so[q]) = pBH[q];
                *(uint4*)(smem + 49152 + so[q]) = pBL[q];
            }
        }
        __syncthreads();

#pragma unroll
        for (int ks = 0; ks < 4; ks++) {
            uint32_t ah[2][4], al[2][4], bb[4][4];
            // A frags (hi and lo)
#pragma unroll
            for (int ma = 0; ma < 2; ma++) {
                int row = wm * 32 + ma * 16 + a_rp;
                int u = (ks * 2 + a_up) ^ (row & 7);
                uint32_t off = (uint32_t)(row * 128 + u * 16);
                ldmx4(ah[ma], sb + off);
                ldmx4(al[ma], sb + 16384 + off);
            }
            // B hi frags: 4 x ldmatrix.x4 -> 8 n-atoms
#pragma unroll
            for (int p = 0; p < 4; p++) {
                int row = wn * 64 + p * 16 + b_rp;
                int u = (ks * 2 + b_up) ^ (row & 7);
                ldmx4(bb[p], sb + 32768 + (uint32_t)(row * 128 + u * 16));
            }
#pragma unroll
            for (int ma = 0; ma < 2; ma++)
#pragma unroll
                for (int na = 0; na < 8; na++) {
                    mma16816(acc[ma][na], ah[ma], &bb[na >> 1][(na & 1) * 2]); // hi*hi
                    mma16816(acc[ma][na], al[ma], &bb[na >> 1][(na & 1) * 2]); // lo*hi
                }
            // B lo frags (overwrite bb)
#pragma unroll
            for (int p = 0; p < 4; p++) {
                int row = wn * 64 + p * 16 + b_rp;
                int u = (ks * 2 + b_up) ^ (row & 7);
                ldmx4(bb[p], sb + 49152 + (uint32_t)(row * 128 + u * 16));
            }
#pragma unroll
            for (int ma = 0; ma < 2; ma++)
#pragma unroll
                for (int na = 0; na < 8; na++)
                    mma16816(acc[ma][na], ah[ma], &bb[na >> 1][(na & 1) * 2]); // hi*lo
        }
    }

    // epilogue: c0,c1 -> row (lane>>2), cols 2*(lane&3)+{0,1}; c2,c3 -> row+8
#pragma unroll
    for (int ma = 0; ma < 2; ma++) {
#pragma unroll
        for (int rh = 0; rh < 2; rh++) {
            const int m = m0 + wm * 32 + ma * 16 + (lane >> 2) + rh * 8;
            const int bbi = m >> 11, sIdx = m & (SS - 1);
#pragma unroll
            for (int na = 0; na < 8; na++) {
                const int e = n0 + wn * 64 + na * 8 + 2 * (lane & 3);
                float v0 = acc[ma][na][rh * 2 + 0] + bias[e];
                float v1 = acc[ma][na][rh * 2 + 1] + bias[e + 1];
                if (mode == 0) {
                    *(float2*)&C[(size_t)m * DM + e] = make_float2(v0, v1);
                } else {
                    int h0 = e >> 6, d0 = e & 63;
                    int h1 = (e + 1) >> 6, d1 = (e + 1) & 63;
                    C[(((size_t)(bbi * NH + h0)) * HD + d0) * SS + sIdx] = v0;
                    C[(((size_t)(bbi * NH + h1)) * HD + d1) * SS + sIdx] = v1;
                }
            }
        }
    }
}

// ---------------- SIMT flash attention (from the 1993us baseline) ----------------
__global__ __launch_bounds__(256) void attn_k(const int* __restrict__ mask)
{
    extern __shared__ float sm[];
    float* Qs = sm;               // [64][68]
    float* Ks = Qs + 64 * 68;     // [64][68]
    float* Ps = Ks + 64 * 68;     // [64][68]
    float* Vs = Ps + 64 * 68;     // [64][64]

    const int tid = threadIdx.x;
    const int tx = tid & 15, ty = tid >> 4;
    const int bh = blockIdx.y;
    const int b = bh >> 4, h = bh & 15;
    const int q0 = blockIdx.x * 64;

    const float* Qh = g_QT + (size_t)bh * HD * SS;
    const float* Kh = g_KT + (size_t)bh * HD * SS;
    const float* Vh = g_V + (size_t)b * SS * DM + h * HD;
    const int* mrow = mask + (size_t)b * SS * SS;

#pragma unroll
    for (int i = 0; i < 4; i++) {
        int f = tid + i * 256;
        int k = f >> 4, rq = (f & 15) << 2;
        *(float4*)&Qs[k * 68 + rq] = *(const float4*)&Qh[(size_t)k * SS + q0 + rq];
    }

    float o[4][4] = {};
    float mr[4], lr[4];
#pragma unroll
    for (int i = 0; i < 4; i++) { mr[i] = -1e30f; lr[i] = 0.f; }
    __syncthreads();

    for (int kv0 = 0; kv0 < SS; kv0 += 64) {
#pragma unroll
        for (int i = 0; i < 4; i++) {
            int f = tid + i * 256;
            int k = f >> 4, cq = (f & 15) << 2;
            *(float4*)&Ks[k * 68 + cq] = *(const float4*)&Kh[(size_t)k * SS + kv0 + cq];
            *(float4*)&Vs[k * 64 + cq] = *(const float4*)&Vh[(size_t)(kv0 + k) * DM + cq];
        }
        __syncthreads();

        float s[4][4] = {};
#pragma unroll 8
        for (int k = 0; k < 64; k++) {
            float a[4], cc[4];
            *(float4*)a  = *(const float4*)&Qs[k * 68 + ty * 4];
            *(float4*)cc = *(const float4*)&Ks[k * 68 + tx * 4];
#pragma unroll
            for (int i = 0; i < 4; i++)
#pragma unroll
                for (int j = 0; j < 4; j++)
                    s[i][j] = fmaf(a[i], cc[j], s[i][j]);
        }

#pragma unroll
        for (int i = 0; i < 4; i++) {
            int q = q0 + ty * 4 + i;
            int4 mm = *(const int4*)&mrow[(size_t)q * SS + kv0 + tx * 4];
            s[i][0] = mm.x ? s[i][0] * 0.125f : -1e9f;
            s[i][1] = mm.y ? s[i][1] * 0.125f : -1e9f;
            s[i][2] = mm.z ? s[i][2] * 0.125f : -1e9f;
            s[i][3] = mm.w ? s[i][3] * 0.125f : -1e9f;
        }

#pragma unroll
        for (int i = 0; i < 4; i++) {
            float mx = fmaxf(fmaxf(s[i][0], s[i][1]), fmaxf(s[i][2], s[i][3]));
#pragma unroll
            for (int off = 8; off; off >>= 1)
                mx = fmaxf(mx, __shfl_xor_sync(0xffffffffu, mx, off));
            float mn = fmaxf(mr[i], mx);
            float corr = __expf(mr[i] - mn);
            float ls = 0.f;
#pragma unroll
            for (int j = 0; j < 4; j++) { s[i][j] = __expf(s[i][j] - mn); ls += s[i][j]; }
#pragma unroll
            for (int off = 8; off; off >>= 1)
                ls += __shfl_xor_sync(0xffffffffu, ls, off);
            lr[i] = lr[i] * corr + ls;
            mr[i] = mn;
#pragma unroll
            for (int j = 0; j < 4; j++) o[i][j] *= corr;
        }

#pragma unroll
        for (int jj = 0; jj < 4; jj++) {
            float4 pv = make_float4(s[0][jj], s[1][jj], s[2][jj], s[3][jj]);
            *(float4*)&Ps[(tx * 4 + jj) * 68 + ty * 4] = pv;
        }
        __syncthreads();

#pragma unroll 8
        for (int j = 0; j < 64; j++) {
            float a[4], vv[4];
            *(float4*)a  = *(const float4*)&Ps[j * 68 + ty * 4];
            *(float4*)vv = *(const float4*)&Vs[j * 64 + tx * 4];
#pragma unroll
            for (int i = 0; i < 4; i++)
#pragma unroll
                for (int d = 0; d < 4; d++)
                    o[i][d] = fmaf(a[i], vv[d], o[i][d]);
        }
        __syncthreads();
    }

#pragma unroll
    for (int i = 0; i < 4; i++) {
        float inv = 1.f / lr[i];
        int q = q0 + ty * 4 + i;
        float4 outv = make_float4(o[i][0] * inv, o[i][1] * inv,
                                  o[i][2] * inv, o[i][3] * inv);
        *(float4*)&g_A[((size_t)(b * SS + q)) * DM + h * HD + tx * 4] = outv;
    }
}

static const int ATTN_SMEM = (3 * 64 * 68 + 64 * 64) * (int)sizeof(float); // 68608
static const int GEMM_SMEM = 65536;

extern "C" void kernel_launch(void* const* d_in, const int* in_sizes, int n_in,
                              void* d_out, int out_size)
{
    const float* Xq  = (const float*)d_in[0];
    const float* Xkv = (const float*)d_in[1];
    const int*   msk = (const int*)d_in[2];
    const float* Wq  = (const float*)d_in[3];
    const float* bq  = (const float*)d_in[4];
    const float* Wk  = (const float*)d_in[5];
    const float* bk  = (const float*)d_in[6];
    const float* Wv  = (const float*)d_in[7];
    const float* bv  = (const float*)d_in[8];
    const float* Wo  = (const float*)d_in[9];
    const float* bo  = (const float*)d_in[10];
    float* out = (float*)d_out;

    float *qt, *ktp, *vf, *ab;
    __nv_bfloat16 *xqh, *xql, *xkh, *xkl, *wh, *wl, *ah, *al;
    cudaGetSymbolAddress((void**)&qt,  g_QT);
    cudaGetSymbolAddress((void**)&ktp, g_KT);
    cudaGetSymbolAddress((void**)&vf,  g_V);
    cudaGetSymbolAddress((void**)&ab,  g_A);
    cudaGetSymbolAddress((void**)&xqh, g_Xq_h);
    cudaGetSymbolAddress((void**)&xql, g_Xq_l);
    cudaGetSymbolAddress((void**)&xkh, g_Xk_h);
    cudaGetSymbolAddress((void**)&xkl, g_Xk_l);
    cudaGetSymbolAddress((void**)&wh,  g_W_h);
    cudaGetSymbolAddress((void**)&wl,  g_W_l);
    cudaGetSymbolAddress((void**)&ah,  g_A_h);
    cudaGetSymbolAddress((void**)&al,  g_A_l);

    cudaFuncSetAttribute(gemm_tc, cudaFuncAttributeMaxDynamicSharedMemorySize, GEMM_SMEM);
    cudaFuncSetAttribute(attn_k,  cudaFuncAttributeMaxDynamicSharedMemorySize, ATTN_SMEM);

    const int n4x = NTOK * DM / 4;
    const int n4w = DM * DM / 4;

    split_k<<<n4x / 256, 256>>>(Xq,  xqh, xql, n4x);
    split_k<<<n4x / 256, 256>>>(Xkv, xkh, xkl, n4x);
    split_k<<<n4w / 256, 256>>>(Wq, wh,               wl,               n4w);
    split_k<<<n4w / 256, 256>>>(Wk, wh + DM * DM,     wl + DM * DM,     n4w);
    split_k<<<n4w / 256, 256>>>(Wv, wh + 2 * DM * DM, wl + 2 * DM * DM, n4w);
    split_k<<<n4w / 256, 256>>>(Wo, wh + 3 * DM * DM, wl + 3 * DM * DM, n4w);

    dim3 gg(DM / 128, NTOK / 128);   // (8, 32)
    gemm_tc<<<gg, 256, GEMM_SMEM>>>(xqh, xql, wh,               wl,               bq, qt,  2);
    gemm_tc<<<gg, 256, GEMM_SMEM>>>(xkh, xkl, wh + DM * DM,     wl + DM * DM,     bk, ktp, 2);
    gemm_tc<<<gg, 256, GEMM_SMEM>>>(xkh, xkl, wh + 2 * DM * DM, wl + 2 * DM * DM, bv, vf,  0);

    attn_k<<<dim3(SS / 64, BB * NH), 256, ATTN_SMEM>>>(msk);

    split_k<<<n4x / 256, 256>>>(ab, ah, al, n4x);
    gemm_tc<<<gg, 256, GEMM_SMEM>>>(ah, al, wh + 3 * DM * DM, wl + 3 * DM * DM, bo, out, 0);
}

// round 7
// speedup vs baseline: 2.1061x; 1.4155x over previous
#include <cuda_runtime.h>
#include <cuda_bf16.h>
#include <cstdint>

// MultiHeadAttention: B=2, S=2048, D=1024, H=16, dh=64, fp32.
// R7: HMMA everywhere. Projections emit bf16 hi/lo [b][h][s][d]; flash
// attention on mma.sync m16n8k16 (QK 3-pass, PV 3-pass hi/lo), P passed
// register-direct (C-frag == A-frag layout). Mask via packed bitmask.

#define DM 1024
#define NH 16
#define HD 64
#define BB 2
#define SS 2048
#define NTOK (BB * SS)

// ---------------- scratch ----------------
__device__ float g_A [NTOK*DM];
__device__ __nv_bfloat16 g_Qh[BB*NH*SS*HD], g_Ql[BB*NH*SS*HD];
__device__ __nv_bfloat16 g_Kh[BB*NH*SS*HD], g_Kl[BB*NH*SS*HD];
__device__ __nv_bfloat16 g_Vh[BB*NH*SS*HD], g_Vl[BB*NH*SS*HD];
__device__ __nv_bfloat16 g_Xq_h[NTOK*DM], g_Xq_l[NTOK*DM];
__device__ __nv_bfloat16 g_Xk_h[NTOK*DM], g_Xk_l[NTOK*DM];
__device__ __nv_bfloat16 g_W_h[4*DM*DM], g_W_l[4*DM*DM];
__device__ __nv_bfloat16 g_A_h[NTOK*DM], g_A_l[NTOK*DM];
__device__ uint32_t g_mb[BB*SS*(SS/32)];

__device__ __forceinline__ uint32_t smem_u32(const void* p) {
    uint32_t a;
    asm("{ .reg .u64 t; cvta.to.shared.u64 t, %1; cvt.u32.u64 %0, t; }" : "=r"(a) : "l"(p));
    return a;
}
__device__ __forceinline__ void ldmx4(uint32_t* r, uint32_t addr) {
    asm volatile("ldmatrix.sync.aligned.m8n8.x4.shared.b16 {%0,%1,%2,%3}, [%4];"
                 : "=r"(r[0]), "=r"(r[1]), "=r"(r[2]), "=r"(r[3]) : "r"(addr));
}
__device__ __forceinline__ void ldmx4t(uint32_t* r, uint32_t addr) {
    asm volatile("ldmatrix.sync.aligned.m8n8.x4.trans.shared.b16 {%0,%1,%2,%3}, [%4];"
                 : "=r"(r[0]), "=r"(r[1]), "=r"(r[2]), "=r"(r[3]) : "r"(addr));
}
__device__ __forceinline__ void mma16816(float* c, const uint32_t* a, const uint32_t* b) {
    asm volatile(
        "mma.sync.aligned.m16n8k16.row.col.f32.bf16.bf16.f32 "
        "{%0,%1,%2,%3}, {%4,%5,%6,%7}, {%8,%9}, {%0,%1,%2,%3};"
        : "+f"(c[0]), "+f"(c[1]), "+f"(c[2]), "+f"(c[3])
        : "r"(a[0]), "r"(a[1]), "r"(a[2]), "r"(a[3]), "r"(b[0]), "r"(b[1]));
}
__device__ __forceinline__ void pack_hl(float a, float b, uint32_t& h, uint32_t& l) {
    __nv_bfloat16 ha = __float2bfloat16_rn(a), hb = __float2bfloat16_rn(b);
    __nv_bfloat162 hv = __halves2bfloat162(ha, hb);
    __nv_bfloat162 lv = __halves2bfloat162(
        __float2bfloat16_rn(a - __bfloat162float(ha)),
        __float2bfloat16_rn(b - __bfloat162float(hb)));
    h = *reinterpret_cast<uint32_t*>(&hv);
    l = *reinterpret_cast<uint32_t*>(&lv);
}

// ---------------- fp32 -> bf16 hi/lo split ----------------
__global__ __launch_bounds__(256) void split_k(
    const float* __restrict__ src, __nv_bfloat16* __restrict__ hi,
    __nv_bfloat16* __restrict__ lo, int n4)
{
    int i = blockIdx.x * blockDim.x + threadIdx.x;
    if (i >= n4) return;
    float4 v = ((const float4*)src)[i];
    float x[4] = {v.x, v.y, v.z, v.w};
    __nv_bfloat16 h[4], l[4];
#pragma unroll
    for (int q = 0; q < 4; q++) {
        h[q] = __float2bfloat16_rn(x[q]);
        l[q] = __float2bfloat16_rn(x[q] - __bfloat162float(h[q]));
    }
    __nv_bfloat162* H = (__nv_bfloat162*)(hi + (size_t)i * 4);
    __nv_bfloat162* L = (__nv_bfloat162*)(lo + (size_t)i * 4);
    H[0] = __halves2bfloat162(h[0], h[1]);
    H[1] = __halves2bfloat162(h[2], h[3]);
    L[0] = __halves2bfloat162(l[0], l[1]);
    L[1] = __halves2bfloat162(l[2], l[3]);
}

// ---------------- mask -> bitmask ----------------
__global__ __launch_bounds__(256) void mask_pack(const int* __restrict__ mask)
{
    int idx = blockIdx.x * 256 + threadIdx.x;   // word over BB*SS*64
    const int4* src = (const int4*)(mask + (size_t)idx * 32);
    uint32_t bits = 0;
#pragma unroll
    for (int j = 0; j < 8; j++) {
        int4 v = src[j];
        bits |= (v.x ? 1u : 0u) << (j * 4);
        bits |= (v.y ? 1u : 0u) << (j * 4 + 1);
        bits |= (v.z ? 1u : 0u) << (j * 4 + 2);
        bits |= (v.w ? 1u : 0u) << (j * 4 + 3);
    }
    g_mb[idx] = bits;
}

// ---------------- HMMA GEMM (validated in R6): C[m,e]=sum_d A[m,d]W[e,d]+b[e] ----------
// mode 0: fp32 flat C; mode 1: bf16 hi/lo to (Ch, Cl) at [b][h][s][d]
__global__ __launch_bounds__(256, 2) void gemm_tc(
    const __nv_bfloat16* __restrict__ Ah, const __nv_bfloat16* __restrict__ Al,
    const __nv_bfloat16* __restrict__ Bh, const __nv_bfloat16* __restrict__ Bl,
    const float* __restrict__ bias, float* __restrict__ C,
    __nv_bfloat16* __restrict__ Ch, __nv_bfloat16* __restrict__ Cl, int mode)
{
    extern __shared__ char smem[];
    const uint32_t sb = smem_u32(smem);
    const int tid = threadIdx.x, lane = tid & 31, wid = tid >> 5;
    const int wm = wid & 3, wn = wid >> 2;
    const int m0 = blockIdx.y * 128, n0 = blockIdx.x * 128;

    float acc[2][8][4] = {};

    const int lrow = tid >> 1, lhalf = tid & 1;
    const size_t arow = (size_t)(m0 + lrow) * DM + lhalf * 32;
    const size_t brow = (size_t)(n0 + lrow) * DM + lhalf * 32;
    uint32_t so[4];
#pragma unroll
    for (int q = 0; q < 4; q++)
        so[q] = lrow * 128 + ((((lhalf * 4 + q) ^ (lrow & 7)) & 7) << 4);

    const int a_rp = (lane & 7) + ((lane >> 3) & 1) * 8;
    const int a_up = (lane >> 4);
    const int b_rp = (lane & 7) + ((lane >> 4) << 3);
    const int b_up = (lane >> 3) & 1;

    for (int c = 0; c < 16; c++) {
        const int kt = c * 64;
        if (c) __syncthreads();
        {
            const uint4* pAH = (const uint4*)(Ah + arow + kt);
            const uint4* pAL = (const uint4*)(Al + arow + kt);
            const uint4* pBH = (const uint4*)(Bh + brow + kt);
            const uint4* pBL = (const uint4*)(Bl + brow + kt);
#pragma unroll
            for (int q = 0; q < 4; q++) {
                *(uint4*)(smem + so[q])         = pAH[q];
                *(uint4*)(smem + 16384 + so[q]) = pAL[q];
                *(uint4*)(smem + 32768 + so[q]) = pBH[q];
                *(uint4*)(smem + 49152 + so[q]) = pBL[q];
            }
        }
        __syncthreads();

#pragma unroll
        for (int ks = 0; ks < 4; ks++) {
            uint32_t ah[2][4], al[2][4], bb[4][4];
#pragma unroll
            for (int ma = 0; ma < 2; ma++) {
                int row = wm * 32 + ma * 16 + a_rp;
                int u = (ks * 2 + a_up) ^ (row & 7);
                uint32_t off = (uint32_t)(row * 128 + u * 16);
                ldmx4(ah[ma], sb + off);
                ldmx4(al[ma], sb + 16384 + off);
            }
#pragma unroll
            for (int p = 0; p < 4; p++) {
                int row = wn * 64 + p * 16 + b_rp;
                int u = (ks * 2 + b_up) ^ (row & 7);
                ldmx4(bb[p], sb + 32768 + (uint32_t)(row * 128 + u * 16));
            }
#pragma unroll
            for (int ma = 0; ma < 2; ma++)
#pragma unroll
                for (int na = 0; na < 8; na++) {
                    mma16816(acc[ma][na], ah[ma], &bb[na >> 1][(na & 1) * 2]);
                    mma16816(acc[ma][na], al[ma], &bb[na >> 1][(na & 1) * 2]);
                }
#pragma unroll
            for (int p = 0; p < 4; p++) {
                int row = wn * 64 + p * 16 + b_rp;
                int u = (ks * 2 + b_up) ^ (row & 7);
                ldmx4(bb[p], sb + 49152 + (uint32_t)(row * 128 + u * 16));
            }
#pragma unroll
            for (int ma = 0; ma < 2; ma++)
#pragma unroll
                for (int na = 0; na < 8; na++)
                    mma16816(acc[ma][na], ah[ma], &bb[na >> 1][(na & 1) * 2]);
        }
    }

#pragma unroll
    for (int ma = 0; ma < 2; ma++) {
#pragma unroll
        for (int rh = 0; rh < 2; rh++) {
            const int m = m0 + wm * 32 + ma * 16 + (lane >> 2) + rh * 8;
            const int bbi = m >> 11, sIdx = m & (SS - 1);
#pragma unroll
            for (int na = 0; na < 8; na++) {
                const int e = n0 + wn * 64 + na * 8 + 2 * (lane & 3);
                float v0 = acc[ma][na][rh * 2 + 0] + bias[e];
                float v1 = acc[ma][na][rh * 2 + 1] + bias[e + 1];
                if (mode == 0) {
                    *(float2*)&C[(size_t)m * DM + e] = make_float2(v0, v1);
                } else {
                    int hh = e >> 6, dd = e & 63;
                    size_t base = (((size_t)(bbi * NH + hh)) * SS + sIdx) * HD + dd;
                    __nv_bfloat16 h0 = __float2bfloat16_rn(v0);
                    __nv_bfloat16 h1 = __float2bfloat16_rn(v1);
                    *(__nv_bfloat162*)(Ch + base) = __halves2bfloat162(h0, h1);
                    *(__nv_bfloat162*)(Cl + base) = __halves2bfloat162(
                        __float2bfloat16_rn(v0 - __bfloat162float(h0)),
                        __float2bfloat16_rn(v1 - __bfloat162float(h1)));
                }
            }
        }
    }
}

// ---------------- HMMA flash attention ----------------
// Grid (SS/64, BB*NH), 128 threads. Warp = 16 q-rows x full kv width.
__global__ __launch_bounds__(128, 2) void attn_tc()
{
    extern __shared__ char smem[];
    const uint32_t sb = smem_u32(smem);
    const uint32_t QH = 0, QL = 8192, KH = 16384, KL = 32768, VH = 49152, VL = 65536;

    const int tid = threadIdx.x, lane = tid & 31, wid = tid >> 5;
    const int bh = blockIdx.y, b = bh >> 4, h = bh & 15;
    const int q0 = blockIdx.x * 64;

    // stage Q (hi/lo) into smem, swizzled 128B rows
    {
        const int r = tid >> 1, half = tid & 1;
        const __nv_bfloat16* qh = g_Qh + ((size_t)bh * SS + q0 + r) * HD + half * 32;
        const __nv_bfloat16* ql = g_Ql + ((size_t)bh * SS + q0 + r) * HD + half * 32;
#pragma unroll
        for (int q = 0; q < 4; q++) {
            uint32_t off = r * 128 + ((((half * 4 + q) ^ (r & 7)) & 7) << 4);
            *(uint4*)(smem + QH + off) = ((const uint4*)qh)[q];
            *(uint4*)(smem + QL + off) = ((const uint4*)ql)[q];
        }
    }
    __syncthreads();

    const int a_rp = (lane & 7) + ((lane >> 3) & 1) * 8;
    const int a_up = (lane >> 4);
    const int b_rp = (lane & 7) + ((lane >> 4) << 3);
    const int b_up = (lane >> 3) & 1;

    uint32_t qah[4][4], qal[4][4];
#pragma unroll
    for (int kc = 0; kc < 4; kc++) {
        int row = wid * 16 + a_rp;
        int u = (kc * 2 + a_up) ^ (row & 7);
        uint32_t off = (uint32_t)(row * 128 + u * 16);
        ldmx4(qah[kc], sb + QH + off);
        ldmx4(qal[kc], sb + QL + off);
    }

    float acc[8][4] = {};
    float m0 = -1e30f, m1 = -1e30f, l0 = 0.f, l1 = 0.f;
    const int gq0 = q0 + wid * 16 + (lane >> 2);
    const int gq1 = gq0 + 8;
    const uint32_t* mrow0 = g_mb + ((size_t)(b * SS) + gq0) * 64;
    const uint32_t* mrow1 = g_mb + ((size_t)(b * SS) + gq1) * 64;

    const __nv_bfloat16* Khg = g_Kh + (size_t)bh * SS * HD;
    const __nv_bfloat16* Klg = g_Kl + (size_t)bh * SS * HD;
    const __nv_bfloat16* Vhg = g_Vh + (size_t)bh * SS * HD;
    const __nv_bfloat16* Vlg = g_Vl + (size_t)bh * SS * HD;

    for (int kv0 = 0; kv0 < SS; kv0 += 128) {
        __syncthreads();
        {
            const int row = tid;
            const size_t gro = (size_t)(kv0 + row) * HD;
            const uint4* pkh = (const uint4*)(Khg + gro);
            const uint4* pkl = (const uint4*)(Klg + gro);
            const uint4* pvh = (const uint4*)(Vhg + gro);
            const uint4* pvl = (const uint4*)(Vlg + gro);
#pragma unroll
            for (int q = 0; q < 8; q++) {
                uint32_t off = row * 128 + ((q ^ (row & 7)) << 4);
                *(uint4*)(smem + KH + off) = pkh[q];
                *(uint4*)(smem + KL + off) = pkl[q];
                *(uint4*)(smem + VH + off) = pvh[q];
                *(uint4*)(smem + VL + off) = pvl[q];
            }
        }
        __syncthreads();

        // S = Q K^T (16 x 128 per warp), 3 passes
        float s[16][4] = {};
#pragma unroll
        for (int kc = 0; kc < 4; kc++) {
            uint32_t kb[8][4];
#pragma unroll
            for (int p = 0; p < 8; p++) {
                int row = p * 16 + b_rp;
                int u = (kc * 2 + b_up) ^ (row & 7);
                ldmx4(kb[p], sb + KH + (uint32_t)(row * 128 + u * 16));
            }
#pragma unroll
            for (int t = 0; t < 16; t++) {
                mma16816(s[t], qah[kc], &kb[t >> 1][(t & 1) * 2]);
                mma16816(s[t], qal[kc], &kb[t >> 1][(t & 1) * 2]);
            }
#pragma unroll
            for (int p = 0; p < 8; p++) {
                int row = p * 16 + b_rp;
                int u = (kc * 2 + b_up) ^ (row & 7);
                ldmx4(kb[p], sb + KL + (uint32_t)(row * 128 + u * 16));
            }
#pragma unroll
            for (int t = 0; t < 16; t++)
                mma16816(s[t], qah[kc], &kb[t >> 1][(t & 1) * 2]);
        }

        // mask + scale
        {
            const int wb = kv0 >> 5;
            uint32_t w0[4], w1[4];
#pragma unroll
            for (int j = 0; j < 4; j++) { w0[j] = mrow0[wb + j]; w1[j] = mrow1[wb + j]; }
            uint32_t allm = w0[0] & w0[1] & w0[2] & w0[3] & w1[0] & w1[1] & w1[2] & w1[3];
            if (allm == 0xFFFFFFFFu) {
#pragma unroll
                for (int t = 0; t < 16; t++) {
                    s[t][0] *= 0.125f; s[t][1] *= 0.125f;
                    s[t][2] *= 0.125f; s[t][3] *= 0.125f;
                }
            } else {
#pragma unroll
                for (int t = 0; t < 16; t++) {
                    int c0 = t * 8 + 2 * (lane & 3), c1 = c0 + 1;
                    s[t][0] = ((w0[c0 >> 5] >> (c0 & 31)) & 1) ? s[t][0] * 0.125f : -1e9f;
                    s[t][1] = ((w0[c1 >> 5] >> (c1 & 31)) & 1) ? s[t][1] * 0.125f : -1e9f;
                    s[t][2] = ((w1[c0 >> 5] >> (c0 & 31)) & 1) ? s[t][2] * 0.125f : -1e9f;
                    s[t][3] = ((w1[c1 >> 5] >> (c1 & 31)) & 1) ? s[t][3] * 0.125f : -1e9f;
                }
            }
        }

        // online softmax (rows owned by 4-lane groups)
        {
            float mx0 = -1e30f, mx1 = -1e30f;
#pragma unroll
            for (int t = 0; t < 16; t++) {
                mx0 = fmaxf(mx0, fmaxf(s[t][0], s[t][1]));
                mx1 = fmaxf(mx1, fmaxf(s[t][2], s[t][3]));
            }
            mx0 = fmaxf(mx0, __shfl_xor_sync(0xffffffffu, mx0, 1));
            mx0 = fmaxf(mx0, __shfl_xor_sync(0xffffffffu, mx0, 2));
            mx1 = fmaxf(mx1, __shfl_xor_sync(0xffffffffu, mx1, 1));
            mx1 = fmaxf(mx1, __shfl_xor_sync(0xffffffffu, mx1, 2));
            float mn0 = fmaxf(m0, mx0), mn1 = fmaxf(m1, mx1);
            float c0f = __expf(m0 - mn0), c1f = __expf(m1 - mn1);
            m0 = mn0; m1 = mn1;
            float ls0 = 0.f, ls1 = 0.f;
#pragma unroll
            for (int t = 0; t < 16; t++) {
                s[t][0] = __expf(s[t][0] - mn0); ls0 += s[t][0];
                s[t][1] = __expf(s[t][1] - mn0); ls0 += s[t][1];
                s[t][2] = __expf(s[t][2] - mn1); ls1 += s[t][2];
                s[t][3] = __expf(s[t][3] - mn1); ls1 += s[t][3];
            }
            l0 = l0 * c0f + ls0; l1 = l1 * c1f + ls1;
#pragma unroll
            for (int t = 0; t < 8; t++) {
                acc[t][0] *= c0f; acc[t][1] *= c0f;
                acc[t][2] *= c1f; acc[t][3] *= c1f;
            }
        }

        // O += P V (P register-direct: C-frag == A-frag layout), 3 passes
#pragma unroll
        for (int kc = 0; kc < 8; kc++) {
            uint32_t pah[4], pal[4];
            pack_hl(s[2 * kc][0],     s[2 * kc][1],     pah[0], pal[0]);
            pack_hl(s[2 * kc][2],     s[2 * kc][3],     pah[1], pal[1]);
            pack_hl(s[2 * kc + 1][0], s[2 * kc + 1][1], pah[2], pal[2]);
            pack_hl(s[2 * kc + 1][2], s[2 * kc + 1][3], pah[3], pal[3]);
            const int vrow = kc * 16 + (((lane >> 3) & 1) << 3) + (lane & 7);
            const int vup = lane >> 4;
#pragma unroll
            for (int g = 0; g < 4; g++) {
                int u = (g * 2 + vup) ^ (vrow & 7);
                uint32_t off = (uint32_t)(vrow * 128 + u * 16);
                uint32_t vb[4];
                ldmx4t(vb, sb + VH + off);
                mma16816(acc[2 * g],     pah, &vb[0]);
                mma16816(acc[2 * g + 1], pah, &vb[2]);
                mma16816(acc[2 * g],     pal, &vb[0]);
                mma16816(acc[2 * g + 1], pal, &vb[2]);
                ldmx4t(vb, sb + VL + off);
                mma16816(acc[2 * g],     pah, &vb[0]);
                mma16816(acc[2 * g + 1], pah, &vb[2]);
            }
        }
    }

    // finalize
    l0 += __shfl_xor_sync(0xffffffffu, l0, 1);
    l0 += __shfl_xor_sync(0xffffffffu, l0, 2);
    l1 += __shfl_xor_sync(0xffffffffu, l1, 1);
    l1 += __shfl_xor_sync(0xffffffffu, l1, 2);
    const float inv0 = 1.f / l0, inv1 = 1.f / l1;
    float* o0 = g_A + ((size_t)(b * SS) + gq0) * DM + h * HD;
    float* o1 = g_A + ((size_t)(b * SS) + gq1) * DM + h * HD;
#pragma unroll
    for (int t = 0; t < 8; t++) {
        int d = t * 8 + 2 * (lane & 3);
        *(float2*)(o0 + d) = make_float2(acc[t][0] * inv0, acc[t][1] * inv0);
        *(float2*)(o1 + d) = make_float2(acc[t][2] * inv1, acc[t][3] * inv1);
    }
}

static const int GEMM_SMEM = 65536;
static const int ATTN_SMEM = 81920;

extern "C" void kernel_launch(void* const* d_in, const int* in_sizes, int n_in,
                              void* d_out, int out_size)
{
    const float* Xq  = (const float*)d_in[0];
    const float* Xkv = (const float*)d_in[1];
    const int*   msk = (const int*)d_in[2];
    const float* Wq  = (const float*)d_in[3];
    const float* bq  = (const float*)d_in[4];
    const float* Wk  = (const float*)d_in[5];
    const float* bk  = (const float*)d_in[6];
    const float* Wv  = (const float*)d_in[7];
    const float* bv  = (const float*)d_in[8];
    const float* Wo  = (const float*)d_in[9];
    const float* bo  = (const float*)d_in[10];
    float* out = (float*)d_out;

    float* ab;
    __nv_bfloat16 *xqh, *xql, *xkh, *xkl, *wh, *wl, *ah, *al;
    __nv_bfloat16 *qh, *ql, *kh, *kl, *vh, *vl;
    cudaGetSymbolAddress((void**)&ab,  g_A);
    cudaGetSymbolAddress((void**)&xqh, g_Xq_h);
    cudaGetSymbolAddress((void**)&xql, g_Xq_l);
    cudaGetSymbolAddress((void**)&xkh, g_Xk_h);
    cudaGetSymbolAddress((void**)&xkl, g_Xk_l);
    cudaGetSymbolAddress((void**)&wh,  g_W_h);
    cudaGetSymbolAddress((void**)&wl,  g_W_l);
    cudaGetSymbolAddress((void**)&ah,  g_A_h);
    cudaGetSymbolAddress((void**)&al,  g_A_l);
    cudaGetSymbolAddress((void**)&qh,  g_Qh);
    cudaGetSymbolAddress((void**)&ql,  g_Ql);
    cudaGetSymbolAddress((void**)&kh,  g_Kh);
    cudaGetSymbolAddress((void**)&kl,  g_Kl);
    cudaGetSymbolAddress((void**)&vh,  g_Vh);
    cudaGetSymbolAddress((void**)&vl,  g_Vl);

    cudaFuncSetAttribute(gemm_tc, cudaFuncAttributeMaxDynamicSharedMemorySize, GEMM_SMEM);
    cudaFuncSetAttribute(attn_tc, cudaFuncAttributeMaxDynamicSharedMemorySize, ATTN_SMEM);

    const int n4x = NTOK * DM / 4;
    const int n4w = DM * DM / 4;

    split_k<<<n4x / 256, 256>>>(Xq,  xqh, xql, n4x);
    split_k<<<n4x / 256, 256>>>(Xkv, xkh, xkl, n4x);
    split_k<<<n4w / 256, 256>>>(Wq, wh,               wl,               n4w);
    split_k<<<n4w / 256, 256>>>(Wk, wh + DM * DM,     wl + DM * DM,     n4w);
    split_k<<<n4w / 256, 256>>>(Wv, wh + 2 * DM * DM, wl + 2 * DM * DM, n4w);
    split_k<<<n4w / 256, 256>>>(Wo, wh + 3 * DM * DM, wl + 3 * DM * DM, n4w);
    mask_pack<<<BB * SS * (SS / 32) / 256, 256>>>(msk);

    dim3 gg(DM / 128, NTOK / 128);   // (8, 32)
    gemm_tc<<<gg, 256, GEMM_SMEM>>>(xqh, xql, wh,               wl,               bq,
                                    nullptr, qh, ql, 1);
    gemm_tc<<<gg, 256, GEMM_SMEM>>>(xkh, xkl, wh + DM * DM,     wl + DM * DM,     bk,
                                    nullptr, kh, kl, 1);
    gemm_tc<<<gg, 256, GEMM_SMEM>>>(xkh, xkl, wh + 2 * DM * DM, wl + 2 * DM * DM, bv,
                                    nullptr, vh, vl, 1);

    attn_tc<<<dim3(SS / 64, BB * NH), 128, ATTN_SMEM>>>();

    split_k<<<n4x / 256, 256>>>(ab, ah, al, n4x);
    gemm_tc<<<gg, 256, GEMM_SMEM>>>(ah, al, wh + 3 * DM * DM, wl + 3 * DM * DM, bo,
                                    out, nullptr, nullptr, 0);
}

// round 8
// speedup vs baseline: 2.4311x; 1.1543x over previous
#include <cuda_runtime.h>
#include <cuda_bf16.h>
#include <cstdint>

// MultiHeadAttention: B=2, S=2048, D=1024, H=16, dh=64, fp32.
// R8: cp.async everywhere, K/V split-wait overlap in attention, QKV fused
// into one launch, attention emits bf16 hi/lo directly (no fp32 round trip).
// mma.sync m16n8k16 bf16 hi/lo 3-pass core unchanged (validated R6/R7).

#define DM 1024
#define NH 16
#define HD 64
#define BB 2
#define SS 2048
#define NTOK (BB * SS)

// ---------------- scratch ----------------
__device__ __nv_bfloat16 g_Qh[BB*NH*SS*HD], g_Ql[BB*NH*SS*HD];
__device__ __nv_bfloat16 g_Kh[BB*NH*SS*HD], g_Kl[BB*NH*SS*HD];
__device__ __nv_bfloat16 g_Vh[BB*NH*SS*HD], g_Vl[BB*NH*SS*HD];
__device__ __nv_bfloat16 g_Xq_h[NTOK*DM], g_Xq_l[NTOK*DM];
__device__ __nv_bfloat16 g_Xk_h[NTOK*DM], g_Xk_l[NTOK*DM];
__device__ __nv_bfloat16 g_W_h[4*DM*DM], g_W_l[4*DM*DM];
__device__ __nv_bfloat16 g_A_h[NTOK*DM], g_A_l[NTOK*DM];
__device__ uint32_t g_mb[BB*SS*(SS/32)];

__device__ __forceinline__ uint32_t smem_u32(const void* p) {
    uint32_t a;
    asm("{ .reg .u64 t; cvta.to.shared.u64 t, %1; cvt.u32.u64 %0, t; }" : "=r"(a) : "l"(p));
    return a;
}
__device__ __forceinline__ void cpa16(uint32_t s, const void* g) {
    asm volatile("cp.async.cg.shared.global [%0], [%1], 16;" :: "r"(s), "l"(g));
}
#define CP_COMMIT() asm volatile("cp.async.commit_group;" ::: "memory")
#define CP_WAIT(n)  asm volatile("cp.async.wait_group %0;" :: "n"(n) : "memory")
__device__ __forceinline__ void ldmx4(uint32_t* r, uint32_t addr) {
    asm volatile("ldmatrix.sync.aligned.m8n8.x4.shared.b16 {%0,%1,%2,%3}, [%4];"
                 : "=r"(r[0]), "=r"(r[1]), "=r"(r[2]), "=r"(r[3]) : "r"(addr));
}
__device__ __forceinline__ void ldmx4t(uint32_t* r, uint32_t addr) {
    asm volatile("ldmatrix.sync.aligned.m8n8.x4.trans.shared.b16 {%0,%1,%2,%3}, [%4];"
                 : "=r"(r[0]), "=r"(r[1]), "=r"(r[2]), "=r"(r[3]) : "r"(addr));
}
__device__ __forceinline__ void mma16816(float* c, const uint32_t* a, const uint32_t* b) {
    asm volatile(
        "mma.sync.aligned.m16n8k16.row.col.f32.bf16.bf16.f32 "
        "{%0,%1,%2,%3}, {%4,%5,%6,%7}, {%8,%9}, {%0,%1,%2,%3};"
        : "+f"(c[0]), "+f"(c[1]), "+f"(c[2]), "+f"(c[3])
        : "r"(a[0]), "r"(a[1]), "r"(a[2]), "r"(a[3]), "r"(b[0]), "r"(b[1]));
}
__device__ __forceinline__ void pack_hl(float a, float b, uint32_t& h, uint32_t& l) {
    __nv_bfloat16 ha = __float2bfloat16_rn(a), hb = __float2bfloat16_rn(b);
    __nv_bfloat162 hv = __halves2bfloat162(ha, hb);
    __nv_bfloat162 lv = __halves2bfloat162(
        __float2bfloat16_rn(a - __bfloat162float(ha)),
        __float2bfloat16_rn(b - __bfloat162float(hb)));
    h = *reinterpret_cast<uint32_t*>(&hv);
    l = *reinterpret_cast<uint32_t*>(&lv);
}

// ---------------- fp32 -> bf16 hi/lo splits (z-fused) ----------------
__device__ __forceinline__ void split_one(const float* src, __nv_bfloat16* hi,
                                          __nv_bfloat16* lo, int i) {
    float4 v = ((const float4*)src)[i];
    float x[4] = {v.x, v.y, v.z, v.w};
    __nv_bfloat16 h[4], l[4];
#pragma unroll
    for (int q = 0; q < 4; q++) {
        h[q] = __float2bfloat16_rn(x[q]);
        l[q] = __float2bfloat16_rn(x[q] - __bfloat162float(h[q]));
    }
    __nv_bfloat162* H = (__nv_bfloat162*)(hi + (size_t)i * 4);
    __nv_bfloat162* L = (__nv_bfloat162*)(lo + (size_t)i * 4);
    H[0] = __halves2bfloat162(h[0], h[1]);
    H[1] = __halves2bfloat162(h[2], h[3]);
    L[0] = __halves2bfloat162(l[0], l[1]);
    L[1] = __halves2bfloat162(l[2], l[3]);
}
__global__ __launch_bounds__(256) void split_x(const float* __restrict__ Xq,
                                               const float* __restrict__ Xkv)
{
    int i = blockIdx.x * 256 + threadIdx.x;
    if (blockIdx.y == 0) split_one(Xq,  g_Xq_h, g_Xq_l, i);
    else                 split_one(Xkv, g_Xk_h, g_Xk_l, i);
}
__global__ __launch_bounds__(256) void split_w(
    const float* __restrict__ Wq, const float* __restrict__ Wk,
    const float* __restrict__ Wv, const float* __restrict__ Wo)
{
    int i = blockIdx.x * 256 + threadIdx.x;
    int z = blockIdx.y;
    const float* src = (z == 0) ? Wq : (z == 1) ? Wk : (z == 2) ? Wv : Wo;
    split_one(src, g_W_h + (size_t)z * DM * DM, g_W_l + (size_t)z * DM * DM, i);
}

// ---------------- mask -> bitmask ----------------
__global__ __launch_bounds__(256) void mask_pack(const int* __restrict__ mask)
{
    int idx = blockIdx.x * 256 + threadIdx.x;
    const int4* src = (const int4*)(mask + (size_t)idx * 32);
    uint32_t bits = 0;
#pragma unroll
    for (int j = 0; j < 8; j++) {
        int4 v = src[j];
        bits |= (v.x ? 1u : 0u) << (j * 4);
        bits |= (v.y ? 1u : 0u) << (j * 4 + 1);
        bits |= (v.z ? 1u : 0u) << (j * 4 + 2);
        bits |= (v.w ? 1u : 0u) << (j * 4 + 3);
    }
    g_mb[idx] = bits;
}

// ---------------- HMMA GEMM body (validated core, cp.async loads) ----------------
// C[m,e] = sum_d A[m,d] W[e,d] + bias[e]
// mode 0: fp32 flat C; mode 1: bf16 hi/lo (Ch, Cl) at [b][h][s][d]
__device__ __forceinline__ void gemm_body(
    const __nv_bfloat16* __restrict__ Ah, const __nv_bfloat16* __restrict__ Al,
    const __nv_bfloat16* __restrict__ Bh, const __nv_bfloat16* __restrict__ Bl,
    const float* __restrict__ bias, float* __restrict__ C,
    __nv_bfloat16* __restrict__ Ch, __nv_bfloat16* __restrict__ Cl, int mode,
    char* smem)
{
    const uint32_t sb = smem_u32(smem);
    const int tid = threadIdx.x, lane = tid & 31, wid = tid >> 5;
    const int wm = wid & 3, wn = wid >> 2;
    const int m0 = blockIdx.y * 128, n0 = blockIdx.x * 128;

    float acc[2][8][4] = {};

    const int lrow = tid >> 1, lhalf = tid & 1;
    const size_t arow = (size_t)(m0 + lrow) * DM + lhalf * 32;
    const size_t brow = (size_t)(n0 + lrow) * DM + lhalf * 32;
    uint32_t so[4];
#pragma unroll
    for (int q = 0; q < 4; q++)
        so[q] = lrow * 128 + ((((lhalf * 4 + q) ^ (lrow & 7)) & 7) << 4);

    const int a_rp = (lane & 7) + ((lane >> 3) & 1) * 8;
    const int a_up = (lane >> 4);
    const int b_rp = (lane & 7) + ((lane >> 4) << 3);
    const int b_up = (lane >> 3) & 1;

    for (int c = 0; c < 16; c++) {
        const int kt = c * 64;
        if (c) __syncthreads();
        {
            const uint4* pAH = (const uint4*)(Ah + arow + kt);
            const uint4* pAL = (const uint4*)(Al + arow + kt);
            const uint4* pBH = (const uint4*)(Bh + brow + kt);
            const uint4* pBL = (const uint4*)(Bl + brow + kt);
#pragma unroll
            for (int q = 0; q < 4; q++) {
                cpa16(sb + so[q],         pAH + q);
                cpa16(sb + 16384 + so[q], pAL + q);
                cpa16(sb + 32768 + so[q], pBH + q);
                cpa16(sb + 49152 + so[q], pBL + q);
            }
        }
        CP_COMMIT();
        CP_WAIT(0);
        __syncthreads();

#pragma unroll
        for (int ks = 0; ks < 4; ks++) {
            uint32_t ah[2][4], al[2][4], bb[4][4];
#pragma unroll
            for (int ma = 0; ma < 2; ma++) {
                int row = wm * 32 + ma * 16 + a_rp;
                int u = (ks * 2 + a_up) ^ (row & 7);
                uint32_t off = (uint32_t)(row * 128 + u * 16);
                ldmx4(ah[ma], sb + off);
                ldmx4(al[ma], sb + 16384 + off);
            }
#pragma unroll
            for (int p = 0; p < 4; p++) {
                int row = wn * 64 + p * 16 + b_rp;
                int u = (ks * 2 + b_up) ^ (row & 7);
                ldmx4(bb[p], sb + 32768 + (uint32_t)(row * 128 + u * 16));
            }
#pragma unroll
            for (int ma = 0; ma < 2; ma++)
#pragma unroll
                for (int na = 0; na < 8; na++) {
                    mma16816(acc[ma][na], ah[ma], &bb[na >> 1][(na & 1) * 2]);
                    mma16816(acc[ma][na], al[ma], &bb[na >> 1][(na & 1) * 2]);
                }
#pragma unroll
            for (int p = 0; p < 4; p++) {
                int row = wn * 64 + p * 16 + b_rp;
                int u = (ks * 2 + b_up) ^ (row & 7);
                ldmx4(bb[p], sb + 49152 + (uint32_t)(row * 128 + u * 16));
            }
#pragma unroll
            for (int ma = 0; ma < 2; ma++)
#pragma unroll
                for (int na = 0; na < 8; na++)
                    mma16816(acc[ma][na], ah[ma], &bb[na >> 1][(na & 1) * 2]);
        }
    }

#pragma unroll
    for (int ma = 0; ma < 2; ma++) {
#pragma unroll
        for (int rh = 0; rh < 2; rh++) {
            const int m = m0 + wm * 32 + ma * 16 + (lane >> 2) + rh * 8;
            const int bbi = m >> 11, sIdx = m & (SS - 1);
#pragma unroll
            for (int na = 0; na < 8; na++) {
                const int e = n0 + wn * 64 + na * 8 + 2 * (lane & 3);
                float v0 = acc[ma][na][rh * 2 + 0] + bias[e];
                float v1 = acc[ma][na][rh * 2 + 1] + bias[e + 1];
                if (mode == 0) {
                    *(float2*)&C[(size_t)m * DM + e] = make_float2(v0, v1);
                } else {
                    int hh = e >> 6, dd = e & 63;
                    size_t base = (((size_t)(bbi * NH + hh)) * SS + sIdx) * HD + dd;
                    __nv_bfloat16 h0 = __float2bfloat16_rn(v0);
                    __nv_bfloat16 h1 = __float2bfloat16_rn(v1);
                    *(__nv_bfloat162*)(Ch + base) = __halves2bfloat162(h0, h1);
                    *(__nv_bfloat162*)(Cl + base) = __halves2bfloat162(
                        __float2bfloat16_rn(v0 - __bfloat162float(h0)),
                        __float2bfloat16_rn(v1 - __bfloat162float(h1)));
                }
            }
        }
    }
}

// fused Q/K/V projections: z selects (A, W, bias, dst)
__global__ __launch_bounds__(256, 2) void gemm_qkv(const float* __restrict__ bq,
                                                   const float* __restrict__ bk,
                                                   const float* __restrict__ bv)
{
    extern __shared__ char smem[];
    const int z = blockIdx.z;
    const __nv_bfloat16* Ah = (z == 0) ? g_Xq_h : g_Xk_h;
    const __nv_bfloat16* Al = (z == 0) ? g_Xq_l : g_Xk_l;
    const __nv_bfloat16* Bh = g_W_h + (size_t)z * DM * DM;
    const __nv_bfloat16* Bl = g_W_l + (size_t)z * DM * DM;
    const float* bias = (z == 0) ? bq : (z == 1) ? bk : bv;
    __nv_bfloat16* Ch = (z == 0) ? g_Qh : (z == 1) ? g_Kh : g_Vh;
    __nv_bfloat16* Cl = (z == 0) ? g_Ql : (z == 1) ? g_Kl : g_Vl;
    gemm_body(Ah, Al, Bh, Bl, bias, nullptr, Ch, Cl, 1, smem);
}

// output projection
__global__ __launch_bounds__(256, 2) void gemm_o(const float* __restrict__ bo,
                                                 float* __restrict__ out)
{
    extern __shared__ char smem[];
    gemm_body(g_A_h, g_A_l, g_W_h + (size_t)3 * DM * DM, g_W_l + (size_t)3 * DM * DM,
              bo, out, nullptr, nullptr, 0, smem);
}

// ---------------- HMMA flash attention (cp.async, K/V split-wait) ----------------
__global__ __launch_bounds__(128, 2) void attn_tc()
{
    extern __shared__ char smem[];
    const uint32_t sb = smem_u32(smem);
    const uint32_t QH = 0, QL = 8192, KH = 16384, KL = 32768, VH = 49152, VL = 65536;

    const int tid = threadIdx.x, lane = tid & 31, wid = tid >> 5;
    const int bh = blockIdx.y, b = bh >> 4, h = bh & 15;
    const int q0 = blockIdx.x * 64;

    {
        const int r = tid >> 1, half = tid & 1;
        const __nv_bfloat16* qh = g_Qh + ((size_t)bh * SS + q0 + r) * HD + half * 32;
        const __nv_bfloat16* ql = g_Ql + ((size_t)bh * SS + q0 + r) * HD + half * 32;
#pragma unroll
        for (int q = 0; q < 4; q++) {
            uint32_t off = r * 128 + ((((half * 4 + q) ^ (r & 7)) & 7) << 4);
            cpa16(sb + QH + off, ((const uint4*)qh) + q);
            cpa16(sb + QL + off, ((const uint4*)ql) + q);
        }
    }
    CP_COMMIT();
    CP_WAIT(0);
    __syncthreads();

    const int a_rp = (lane & 7) + ((lane >> 3) & 1) * 8;
    const int a_up = (lane >> 4);
    const int b_rp = (lane & 7) + ((lane >> 4) << 3);
    const int b_up = (lane >> 3) & 1;

    uint32_t qah[4][4], qal[4][4];
#pragma unroll
    for (int kc = 0; kc < 4; kc++) {
        int row = wid * 16 + a_rp;
        int u = (kc * 2 + a_up) ^ (row & 7);
        uint32_t off = (uint32_t)(row * 128 + u * 16);
        ldmx4(qah[kc], sb + QH + off);
        ldmx4(qal[kc], sb + QL + off);
    }

    float acc[8][4] = {};
    float m0 = -1e30f, m1 = -1e30f, l0 = 0.f, l1 = 0.f;
    const int gq0 = q0 + wid * 16 + (lane >> 2);
    const int gq1 = gq0 + 8;
    const uint32_t* mrow0 = g_mb + ((size_t)(b * SS) + gq0) * 64;
    const uint32_t* mrow1 = g_mb + ((size_t)(b * SS) + gq1) * 64;

    const __nv_bfloat16* Khg = g_Kh + (size_t)bh * SS * HD;
    const __nv_bfloat16* Klg = g_Kl + (size_t)bh * SS * HD;
    const __nv_bfloat16* Vhg = g_Vh + (size_t)bh * SS * HD;
    const __nv_bfloat16* Vlg = g_Vl + (size_t)bh * SS * HD;

    for (int kv0 = 0; kv0 < SS; kv0 += 128) {
        __syncthreads();   // prior PV reads done; buffers reusable
        {
            const int row = tid;
            const size_t gro = (size_t)(kv0 + row) * HD;
            const uint4* pkh = (const uint4*)(Khg + gro);
            const uint4* pkl = (const uint4*)(Klg + gro);
            const uint4* pvh = (const uint4*)(Vhg + gro);
            const uint4* pvl = (const uint4*)(Vlg + gro);
#pragma unroll
            for (int q = 0; q < 8; q++) {
                uint32_t off = row * 128 + ((q ^ (row & 7)) << 4);
                cpa16(sb + KH + off, pkh + q);
                cpa16(sb + KL + off, pkl + q);
            }
            CP_COMMIT();   // group: K
#pragma unroll
            for (int q = 0; q < 8; q++) {
                uint32_t off = row * 128 + ((q ^ (row & 7)) << 4);
                cpa16(sb + VH + off, pvh + q);
                cpa16(sb + VL + off, pvl + q);
            }
            CP_COMMIT();   // group: V
        }
        CP_WAIT(1);        // K complete; V may still be in flight
        __syncthreads();

        // S = Q K^T (16 x 128 per warp), 3 passes
        float s[16][4] = {};
#pragma unroll
        for (int kc = 0; kc < 4; kc++) {
            uint32_t kb[8][4];
#pragma unroll
            for (int p = 0; p < 8; p++) {
                int row = p * 16 + b_rp;
                int u = (kc * 2 + b_up) ^ (row & 7);
                ldmx4(kb[p], sb + KH + (uint32_t)(row * 128 + u * 16));
            }
#pragma unroll
            for (int t = 0; t < 16; t++) {
                mma16816(s[t], qah[kc], &kb[t >> 1][(t & 1) * 2]);
                mma16816(s[t], qal[kc], &kb[t >> 1][(t & 1) * 2]);
            }
#pragma unroll
            for (int p = 0; p < 8; p++) {
                int row = p * 16 + b_rp;
                int u = (kc * 2 + b_up) ^ (row & 7);
                ldmx4(kb[p], sb + KL + (uint32_t)(row * 128 + u * 16));
            }
#pragma unroll
            for (int t = 0; t < 16; t++)
                mma16816(s[t], qah[kc], &kb[t >> 1][(t & 1) * 2]);
        }

        // mask + scale
        {
            const int wb = kv0 >> 5;
            uint32_t w0[4], w1[4];
#pragma unroll
            for (int j = 0; j < 4; j++) { w0[j] = mrow0[wb + j]; w1[j] = mrow1[wb + j]; }
            uint32_t allm = w0[0] & w0[1] & w0[2] & w0[3] & w1[0] & w1[1] & w1[2] & w1[3];
            if (allm == 0xFFFFFFFFu) {
#pragma unroll
                for (int t = 0; t < 16; t++) {
                    s[t][0] *= 0.125f; s[t][1] *= 0.125f;
                    s[t][2] *= 0.125f; s[t][3] *= 0.125f;
                }
            } else {
#pragma unroll
                for (int t = 0; t < 16; t++) {
                    int c0 = t * 8 + 2 * (lane & 3), c1 = c0 + 1;
                    s[t][0] = ((w0[c0 >> 5] >> (c0 & 31)) & 1) ? s[t][0] * 0.125f : -1e9f;
                    s[t][1] = ((w0[c1 >> 5] >> (c1 & 31)) & 1) ? s[t][1] * 0.125f : -1e9f;
                    s[t][2] = ((w1[c0 >> 5] >> (c0 & 31)) & 1) ? s[t][2] * 0.125f : -1e9f;
                    s[t][3] = ((w1[c1 >> 5] >> (c1 & 31)) & 1) ? s[t][3] * 0.125f : -1e9f;
                }
            }
        }

        // online softmax (rows owned by 4-lane groups)
        {
            float mx0 = -1e30f, mx1 = -1e30f;
#pragma unroll
            for (int t = 0; t < 16; t++) {
                mx0 = fmaxf(mx0, fmaxf(s[t][0], s[t][1]));
                mx1 = fmaxf(mx1, fmaxf(s[t][2], s[t][3]));
            }
            mx0 = fmaxf(mx0, __shfl_xor_sync(0xffffffffu, mx0, 1));
            mx0 = fmaxf(mx0, __shfl_xor_sync(0xffffffffu, mx0, 2));
            mx1 = fmaxf(mx1, __shfl_xor_sync(0xffffffffu, mx1, 1));
            mx1 = fmaxf(mx1, __shfl_xor_sync(0xffffffffu, mx1, 2));
            float mn0 = fmaxf(m0, mx0), mn1 = fmaxf(m1, mx1);
            float c0f = __expf(m0 - mn0), c1f = __expf(m1 - mn1);
            m0 = mn0; m1 = mn1;
            float ls0 = 0.f, ls1 = 0.f;
#pragma unroll
            for (int t = 0; t < 16; t++) {
                s[t][0] = __expf(s[t][0] - mn0); ls0 += s[t][0];
                s[t][1] = __expf(s[t][1] - mn0); ls0 += s[t][1];
                s[t][2] = __expf(s[t][2] - mn1); ls1 += s[t][2];
                s[t][3] = __expf(s[t][3] - mn1); ls1 += s[t][3];
            }
            l0 = l0 * c0f + ls0; l1 = l1 * c1f + ls1;
#pragma unroll
            for (int t = 0; t < 8; t++) {
                acc[t][0] *= c0f; acc[t][1] *= c0f;
                acc[t][2] *= c1f; acc[t][3] *= c1f;
            }
        }

        CP_WAIT(0);        // V landed (overlapped with QK + softmax)
        __syncthreads();

        // O += P V (register-direct P), 3 passes
#pragma unroll
        for (int kc = 0; kc < 8; kc++) {
            uint32_t pah[4], pal[4];
            pack_hl(s[2 * kc][0],     s[2 * kc][1],     pah[0], pal[0]);
            pack_hl(s[2 * kc][2],     s[2 * kc][3],     pah[1], pal[1]);
            pack_hl(s[2 * kc + 1][0], s[2 * kc + 1][1], pah[2], pal[2]);
            pack_hl(s[2 * kc + 1][2], s[2 * kc + 1][3], pah[3], pal[3]);
            const int vrow = kc * 16 + (((lane >> 3) & 1) << 3) + (lane & 7);
            const int vup = lane >> 4;
#pragma unroll
            for (int g = 0; g < 4; g++) {
                int u = (g * 2 + vup) ^ (vrow & 7);
                uint32_t off = (uint32_t)(vrow * 128 + u * 16);
                uint32_t vb[4];
                ldmx4t(vb, sb + VH + off);
                mma16816(acc[2 * g],     pah, &vb[0]);
                mma16816(acc[2 * g + 1], pah, &vb[2]);
                mma16816(acc[2 * g],     pal, &vb[0]);
                mma16816(acc[2 * g + 1], pal, &vb[2]);
                ldmx4t(vb, sb + VL + off);
                mma16816(acc[2 * g],     pah, &vb[0]);
                mma16816(acc[2 * g + 1], pah, &vb[2]);
            }
        }
    }

    // finalize -> bf16 hi/lo directly (feeds O projection)
    l0 += __shfl_xor_sync(0xffffffffu, l0, 1);
    l0 += __shfl_xor_sync(0xffffffffu, l0, 2);
    l1 += __shfl_xor_sync(0xffffffffu, l1, 1);
    l1 += __shfl_xor_sync(0xffffffffu, l1, 2);
    const float inv0 = 1.f / l0, inv1 = 1.f / l1;
    const size_t o0 = ((size_t)(b * SS) + gq0) * DM + h * HD;
    const size_t o1 = ((size_t)(b * SS) + gq1) * DM + h * HD;
#pragma unroll
    for (int t = 0; t < 8; t++) {
        int d = t * 8 + 2 * (lane & 3);
        uint32_t hh, ll;
        pack_hl(acc[t][0] * inv0, acc[t][1] * inv0, hh, ll);
        *(uint32_t*)(g_A_h + o0 + d) = hh;
        *(uint32_t*)(g_A_l + o0 + d) = ll;
        pack_hl(acc[t][2] * inv1, acc[t][3] * inv1, hh, ll);
        *(uint32_t*)(g_A_h + o1 + d) = hh;
        *(uint32_t*)(g_A_l + o1 + d) = ll;
    }
}

static const int GEMM_SMEM = 65536;
static const int ATTN_SMEM = 81920;

extern "C" void kernel_launch(void* const* d_in, const int* in_sizes, int n_in,
                              void* d_out, int out_size)
{
    const float* Xq  = (const float*)d_in[0];
    const float* Xkv = (const float*)d_in[1];
    const int*   msk = (const int*)d_in[2];
    const float* Wq  = (const float*)d_in[3];
    const float* bq  = (const float*)d_in[4];
    const float* Wk  = (const float*)d_in[5];
    const float* bk  = (const float*)d_in[6];
    const float* Wv  = (const float*)d_in[7];
    const float* bv  = (const float*)d_in[8];
    const float* Wo  = (const float*)d_in[9];
    const float* bo  = (const float*)d_in[10];
    float* out = (float*)d_out;

    cudaFuncSetAttribute(gemm_qkv, cudaFuncAttributeMaxDynamicSharedMemorySize, GEMM_SMEM);
    cudaFuncSetAttribute(gemm_o,   cudaFuncAttributeMaxDynamicSharedMemorySize, GEMM_SMEM);
    cudaFuncSetAttribute(attn_tc,  cudaFuncAttributeMaxDynamicSharedMemorySize, ATTN_SMEM);

    const int n4x = NTOK * DM / 4;   // 1,048,576
    const int n4w = DM * DM / 4;     // 262,144

    split_x<<<dim3(n4x / 256, 2), 256>>>(Xq, Xkv);
    split_w<<<dim3(n4w / 256, 4), 256>>>(Wq, Wk, Wv, Wo);
    mask_pack<<<BB * SS * (SS / 32) / 256, 256>>>(msk);

    gemm_qkv<<<dim3(DM / 128, NTOK / 128, 3), 256, GEMM_SMEM>>>(bq, bk, bv);
    attn_tc<<<dim3(SS / 64, BB * NH), 128, ATTN_SMEM>>>();
    gemm_o<<<dim3(DM / 128, NTOK / 128), 256, GEMM_SMEM>>>(bo, out);
}

// round 9
// speedup vs baseline: 2.8202x; 1.1600x over previous
#include <cuda_runtime.h>
#include <cuda_bf16.h>
#include <cstdint>

// MultiHeadAttention: B=2, S=2048, D=1024, H=16, dh=64, fp32.
// R9: 2-stage cp.async pipelines. GEMM packs hi|lo in one 128B row (K-chunk 32)
// so double buffering fits in 64KB (occ 2 kept). Attention kv-chunk 64 with
// K+V fully double-buffered in the same 80KB. mma core unchanged (R6/R7).

#define DM 1024
#define NH 16
#define HD 64
#define BB 2
#define SS 2048
#define NTOK (BB * SS)

// ---------------- scratch ----------------
__device__ __nv_bfloat16 g_Qh[BB*NH*SS*HD], g_Ql[BB*NH*SS*HD];
__device__ __nv_bfloat16 g_Kh[BB*NH*SS*HD], g_Kl[BB*NH*SS*HD];
__device__ __nv_bfloat16 g_Vh[BB*NH*SS*HD], g_Vl[BB*NH*SS*HD];
__device__ __nv_bfloat16 g_Xq_h[NTOK*DM], g_Xq_l[NTOK*DM];
__device__ __nv_bfloat16 g_Xk_h[NTOK*DM], g_Xk_l[NTOK*DM];
__device__ __nv_bfloat16 g_W_h[4*DM*DM], g_W_l[4*DM*DM];
__device__ __nv_bfloat16 g_A_h[NTOK*DM], g_A_l[NTOK*DM];
__device__ uint32_t g_mb[BB*SS*(SS/32)];

__device__ __forceinline__ uint32_t smem_u32(const void* p) {
    uint32_t a;
    asm("{ .reg .u64 t; cvta.to.shared.u64 t, %1; cvt.u32.u64 %0, t; }" : "=r"(a) : "l"(p));
    return a;
}
__device__ __forceinline__ void cpa16(uint32_t s, const void* g) {
    asm volatile("cp.async.cg.shared.global [%0], [%1], 16;" :: "r"(s), "l"(g));
}
#define CP_COMMIT() asm volatile("cp.async.commit_group;" ::: "memory")
#define CP_WAIT(n)  asm volatile("cp.async.wait_group %0;" :: "n"(n) : "memory")
__device__ __forceinline__ void ldmx4(uint32_t* r, uint32_t addr) {
    asm volatile("ldmatrix.sync.aligned.m8n8.x4.shared.b16 {%0,%1,%2,%3}, [%4];"
                 : "=r"(r[0]), "=r"(r[1]), "=r"(r[2]), "=r"(r[3]) : "r"(addr));
}
__device__ __forceinline__ void ldmx4t(uint32_t* r, uint32_t addr) {
    asm volatile("ldmatrix.sync.aligned.m8n8.x4.trans.shared.b16 {%0,%1,%2,%3}, [%4];"
                 : "=r"(r[0]), "=r"(r[1]), "=r"(r[2]), "=r"(r[3]) : "r"(addr));
}
__device__ __forceinline__ void mma16816(float* c, const uint32_t* a, const uint32_t* b) {
    asm volatile(
        "mma.sync.aligned.m16n8k16.row.col.f32.bf16.bf16.f32 "
        "{%0,%1,%2,%3}, {%4,%5,%6,%7}, {%8,%9}, {%0,%1,%2,%3};"
        : "+f"(c[0]), "+f"(c[1]), "+f"(c[2]), "+f"(c[3])
        : "r"(a[0]), "r"(a[1]), "r"(a[2]), "r"(a[3]), "r"(b[0]), "r"(b[1]));
}
__device__ __forceinline__ void pack_hl(float a, float b, uint32_t& h, uint32_t& l) {
    __nv_bfloat16 ha = __float2bfloat16_rn(a), hb = __float2bfloat16_rn(b);
    __nv_bfloat162 hv = __halves2bfloat162(ha, hb);
    __nv_bfloat162 lv = __halves2bfloat162(
        __float2bfloat16_rn(a - __bfloat162float(ha)),
        __float2bfloat16_rn(b - __bfloat162float(hb)));
    h = *reinterpret_cast<uint32_t*>(&hv);
    l = *reinterpret_cast<uint32_t*>(&lv);
}

// ---------------- fp32 -> bf16 hi/lo splits (z-fused) ----------------
__device__ __forceinline__ void split_one(const float* src, __nv_bfloat16* hi,
                                          __nv_bfloat16* lo, int i) {
    float4 v = ((const float4*)src)[i];
    float x[4] = {v.x, v.y, v.z, v.w};
    __nv_bfloat16 h[4], l[4];
#pragma unroll
    for (int q = 0; q < 4; q++) {
        h[q] = __float2bfloat16_rn(x[q]);
        l[q] = __float2bfloat16_rn(x[q] - __bfloat162float(h[q]));
    }
    __nv_bfloat162* H = (__nv_bfloat162*)(hi + (size_t)i * 4);
    __nv_bfloat162* L = (__nv_bfloat162*)(lo + (size_t)i * 4);
    H[0] = __halves2bfloat162(h[0], h[1]);
    H[1] = __halves2bfloat162(h[2], h[3]);
    L[0] = __halves2bfloat162(l[0], l[1]);
    L[1] = __halves2bfloat162(l[2], l[3]);
}
__global__ __launch_bounds__(256) void split_x(const float* __restrict__ Xq,
                                               const float* __restrict__ Xkv)
{
    int i = blockIdx.x * 256 + threadIdx.x;
    if (blockIdx.y == 0) split_one(Xq,  g_Xq_h, g_Xq_l, i);
    else                 split_one(Xkv, g_Xk_h, g_Xk_l, i);
}
__global__ __launch_bounds__(256) void split_w(
    const float* __restrict__ Wq, const float* __restrict__ Wk,
    const float* __restrict__ Wv, const float* __restrict__ Wo)
{
    int i = blockIdx.x * 256 + threadIdx.x;
    int z = blockIdx.y;
    const float* src = (z == 0) ? Wq : (z == 1) ? Wk : (z == 2) ? Wv : Wo;
    split_one(src, g_W_h + (size_t)z * DM * DM, g_W_l + (size_t)z * DM * DM, i);
}

// ---------------- mask -> bitmask ----------------
__global__ __launch_bounds__(256) void mask_pack(const int* __restrict__ mask)
{
    int idx = blockIdx.x * 256 + threadIdx.x;
    const int4* src = (const int4*)(mask + (size_t)idx * 32);
    uint32_t bits = 0;
#pragma unroll
    for (int j = 0; j < 8; j++) {
        int4 v = src[j];
        bits |= (v.x ? 1u : 0u) << (j * 4);
        bits |= (v.y ? 1u : 0u) << (j * 4 + 1);
        bits |= (v.z ? 1u : 0u) << (j * 4 + 2);
        bits |= (v.w ? 1u : 0u) << (j * 4 + 3);
    }
    g_mb[idx] = bits;
}

// ---------------- HMMA GEMM, 2-stage pipeline ----------------
// Row layout per tile row (128B): [32 bf16 hi | 32 bf16 lo], K-chunk 32.
// Stage st: A at st*32768, B at st*32768 + 16384. 2 stages = 64KB.
__device__ __forceinline__ void gemm_load_chunk(
    uint32_t sb, int st,
    const __nv_bfloat16* Ah, const __nv_bfloat16* Al,
    const __nv_bfloat16* Bh, const __nv_bfloat16* Bl,
    int m0, int n0, int kt, int tid)
{
    const int r = tid >> 1, half = tid & 1;
    const uint32_t ab = sb + st * 32768;
    const uint32_t bbp = ab + 16384;
    const size_t arow = (size_t)(m0 + r) * DM + kt;
    const size_t brow = (size_t)(n0 + r) * DM + kt;
#pragma unroll
    for (int q = 0; q < 2; q++) {
        const int lu = half * 2 + q;                 // logical unit 0..3
        const uint32_t hOff = r * 128 + ((lu ^ (r & 7)) << 4);
        const uint32_t lOff = r * 128 + (((4 + lu) ^ (r & 7)) << 4);
        cpa16(ab + hOff,  Ah + arow + lu * 8);
        cpa16(ab + lOff,  Al + arow + lu * 8);
        cpa16(bbp + hOff, Bh + brow + lu * 8);
        cpa16(bbp + lOff, Bl + brow + lu * 8);
    }
}

__device__ __forceinline__ void gemm_body(
    const __nv_bfloat16* __restrict__ Ah, const __nv_bfloat16* __restrict__ Al,
    const __nv_bfloat16* __restrict__ Bh, const __nv_bfloat16* __restrict__ Bl,
    const float* __restrict__ bias, float* __restrict__ C,
    __nv_bfloat16* __restrict__ Ch, __nv_bfloat16* __restrict__ Cl, int mode,
    char* smem)
{
    const uint32_t sb = smem_u32(smem);
    const int tid = threadIdx.x, lane = tid & 31, wid = tid >> 5;
    const int wm = wid & 3, wn = wid >> 2;
    const int m0 = blockIdx.y * 128, n0 = blockIdx.x * 128;

    float acc[2][8][4] = {};

    const int a_rp = (lane & 7) + ((lane >> 3) & 1) * 8;
    const int a_up = (lane >> 4);
    const int b_rp = (lane & 7) + ((lane >> 4) << 3);
    const int b_up = (lane >> 3) & 1;

    const int NC = DM / 32;   // 32 chunks
    gemm_load_chunk(sb, 0, Ah, Al, Bh, Bl, m0, n0, 0, tid);
    CP_COMMIT();

    for (int c = 0; c < NC; c++) {
        if (c + 1 < NC) {
            gemm_load_chunk(sb, (c + 1) & 1, Ah, Al, Bh, Bl, m0, n0, (c + 1) * 32, tid);
            CP_COMMIT();
            CP_WAIT(1);
        } else {
            CP_WAIT(0);
        }
        __syncthreads();

        const uint32_t ab = sb + (c & 1) * 32768;
        const uint32_t bbp = ab + 16384;
#pragma unroll
        for (int ks = 0; ks < 2; ks++) {
            uint32_t ah[2][4], al[2][4], bb[4][4];
#pragma unroll
            for (int ma = 0; ma < 2; ma++) {
                int row = wm * 32 + ma * 16 + a_rp;
                uint32_t roff = (uint32_t)(row * 128);
                ldmx4(ah[ma], ab + roff + ((((ks * 2 + a_up)) ^ (row & 7)) << 4));
                ldmx4(al[ma], ab + roff + (((4 + ks * 2 + a_up) ^ (row & 7)) << 4));
            }
#pragma unroll
            for (int p = 0; p < 4; p++) {
                int row = wn * 64 + p * 16 + b_rp;
                ldmx4(bb[p], bbp + (uint32_t)(row * 128) +
                             ((((ks * 2 + b_up)) ^ (row & 7)) << 4));
            }
#pragma unroll
            for (int ma = 0; ma < 2; ma++)
#pragma unroll
                for (int na = 0; na < 8; na++) {
                    mma16816(acc[ma][na], ah[ma], &bb[na >> 1][(na & 1) * 2]);
                    mma16816(acc[ma][na], al[ma], &bb[na >> 1][(na & 1) * 2]);
                }
#pragma unroll
            for (int p = 0; p < 4; p++) {
                int row = wn * 64 + p * 16 + b_rp;
                ldmx4(bb[p], bbp + (uint32_t)(row * 128) +
                             (((4 + ks * 2 + b_up) ^ (row & 7)) << 4));
            }
#pragma unroll
            for (int ma = 0; ma < 2; ma++)
#pragma unroll
                for (int na = 0; na < 8; na++)
                    mma16816(acc[ma][na], ah[ma], &bb[na >> 1][(na & 1) * 2]);
        }
        __syncthreads();
    }

#pragma unroll
    for (int ma = 0; ma < 2; ma++) {
#pragma unroll
        for (int rh = 0; rh < 2; rh++) {
            const int m = m0 + wm * 32 + ma * 16 + (lane >> 2) + rh * 8;
            const int bbi = m >> 11, sIdx = m & (SS - 1);
#pragma unroll
            for (int na = 0; na < 8; na++) {
                const int e = n0 + wn * 64 + na * 8 + 2 * (lane & 3);
                float v0 = acc[ma][na][rh * 2 + 0] + bias[e];
                float v1 = acc[ma][na][rh * 2 + 1] + bias[e + 1];
                if (mode == 0) {
                    *(float2*)&C[(size_t)m * DM + e] = make_float2(v0, v1);
                } else {
                    int hh = e >> 6, dd = e & 63;
                    size_t base = (((size_t)(bbi * NH + hh)) * SS + sIdx) * HD + dd;
                    __nv_bfloat16 h0 = __float2bfloat16_rn(v0);
                    __nv_bfloat16 h1 = __float2bfloat16_rn(v1);
                    *(__nv_bfloat162*)(Ch + base) = __halves2bfloat162(h0, h1);
                    *(__nv_bfloat162*)(Cl + base) = __halves2bfloat162(
                        __float2bfloat16_rn(v0 - __bfloat162float(h0)),
                        __float2bfloat16_rn(v1 - __bfloat162float(h1)));
                }
            }
        }
    }
}

__global__ __launch_bounds__(256, 2) void gemm_qkv(const float* __restrict__ bq,
                                                   const float* __restrict__ bk,
                                                   const float* __restrict__ bv)
{
    extern __shared__ char smem[];
    const int z = blockIdx.z;
    const __nv_bfloat16* Ah = (z == 0) ? g_Xq_h : g_Xk_h;
    const __nv_bfloat16* Al = (z == 0) ? g_Xq_l : g_Xk_l;
    const __nv_bfloat16* Bh = g_W_h + (size_t)z * DM * DM;
    const __nv_bfloat16* Bl = g_W_l + (size_t)z * DM * DM;
    const float* bias = (z == 0) ? bq : (z == 1) ? bk : bv;
    __nv_bfloat16* Ch = (z == 0) ? g_Qh : (z == 1) ? g_Kh : g_Vh;
    __nv_bfloat16* Cl = (z == 0) ? g_Ql : (z == 1) ? g_Kl : g_Vl;
    gemm_body(Ah, Al, Bh, Bl, bias, nullptr, Ch, Cl, 1, smem);
}

__global__ __launch_bounds__(256, 2) void gemm_o(const float* __restrict__ bo,
                                                 float* __restrict__ out)
{
    extern __shared__ char smem[];
    gemm_body(g_A_h, g_A_l, g_W_h + (size_t)3 * DM * DM, g_W_l + (size_t)3 * DM * DM,
              bo, out, nullptr, nullptr, 0, smem);
}

// ---------------- HMMA flash attention, 2-stage K+V pipeline, kv-chunk 64 ------------
// smem: QH 0, QL 8192; stage st: K at 16384+st*16384 (KH, KL+8192);
//       V at 49152+st*16384 (VH, VL+8192). Total 81920.
__device__ __forceinline__ void attn_load_chunk(
    uint32_t sb, int st,
    const __nv_bfloat16* Khg, const __nv_bfloat16* Klg,
    const __nv_bfloat16* Vhg, const __nv_bfloat16* Vlg,
    int kv0, int tid)
{
    const int r = tid >> 1, half = tid & 1;   // 64 rows x 2 halves
    const uint32_t kb = sb + 16384 + st * 16384;
    const uint32_t vb = sb + 49152 + st * 16384;
    const size_t gro = (size_t)(kv0 + r) * HD + half * 32;
#pragma unroll
    for (int q = 0; q < 4; q++) {
        const uint32_t off = r * 128 + ((((half * 4 + q) ^ (r & 7)) & 7) << 4);
        cpa16(kb + off,        ((const uint4*)(Khg + gro)) + q);
        cpa16(kb + 8192 + off, ((const uint4*)(Klg + gro)) + q);
        cpa16(vb + off,        ((const uint4*)(Vhg + gro)) + q);
        cpa16(vb + 8192 + off, ((const uint4*)(Vlg + gro)) + q);
    }
}

__global__ __launch_bounds__(128, 2) void attn_tc()
{
    extern __shared__ char smem[];
    const uint32_t sb = smem_u32(smem);
    const uint32_t QH = 0, QL = 8192;

    const int tid = threadIdx.x, lane = tid & 31, wid = tid >> 5;
    const int bh = blockIdx.y, b = bh >> 4, h = bh & 15;
    const int q0 = blockIdx.x * 64;

    const __nv_bfloat16* Khg = g_Kh + (size_t)bh * SS * HD;
    const __nv_bfloat16* Klg = g_Kl + (size_t)bh * SS * HD;
    const __nv_bfloat16* Vhg = g_Vh + (size_t)bh * SS * HD;
    const __nv_bfloat16* Vlg = g_Vl + (size_t)bh * SS * HD;

    // Q stage + chunk 0 prefetch
    {
        const int r = tid >> 1, half = tid & 1;
        const __nv_bfloat16* qh = g_Qh + ((size_t)bh * SS + q0 + r) * HD + half * 32;
        const __nv_bfloat16* ql = g_Ql + ((size_t)bh * SS + q0 + r) * HD + half * 32;
#pragma unroll
        for (int q = 0; q < 4; q++) {
            uint32_t off = r * 128 + ((((half * 4 + q) ^ (r & 7)) & 7) << 4);
            cpa16(sb + QH + off, ((const uint4*)qh) + q);
            cpa16(sb + QL + off, ((const uint4*)ql) + q);
        }
    }
    CP_COMMIT();
    attn_load_chunk(sb, 0, Khg, Klg, Vhg, Vlg, 0, tid);
    CP_COMMIT();
    CP_WAIT(1);           // Q ready
    __syncthreads();

    const int a_rp = (lane & 7) + ((lane >> 3) & 1) * 8;
    const int a_up = (lane >> 4);
    const int b_rp = (lane & 7) + ((lane >> 4) << 3);
    const int b_up = (lane >> 3) & 1;

    uint32_t qah[4][4], qal[4][4];
#pragma unroll
    for (int kc = 0; kc < 4; kc++) {
        int row = wid * 16 + a_rp;
        int u = (kc * 2 + a_up) ^ (row & 7);
        uint32_t off = (uint32_t)(row * 128 + u * 16);
        ldmx4(qah[kc], sb + QH + off);
        ldmx4(qal[kc], sb + QL + off);
    }

    float acc[8][4] = {};
    float m0 = -1e30f, m1 = -1e30f, l0 = 0.f, l1 = 0.f;
    const int gq0 = q0 + wid * 16 + (lane >> 2);
    const int gq1 = gq0 + 8;
    const uint32_t* mrow0 = g_mb + ((size_t)(b * SS) + gq0) * 64;
    const uint32_t* mrow1 = g_mb + ((size_t)(b * SS) + gq1) * 64;

    const int NC = SS / 64;   // 32 chunks
    for (int c = 0; c < NC; c++) {
        if (c + 1 < NC) {
            attn_load_chunk(sb, (c + 1) & 1, Khg, Klg, Vhg, Vlg, (c + 1) * 64, tid);
            CP_COMMIT();
            CP_WAIT(1);
        } else {
            CP_WAIT(0);
        }
        __syncthreads();

        const uint32_t kbase = sb + 16384 + (c & 1) * 16384;
        const uint32_t vbase = sb + 49152 + (c & 1) * 16384;

        // S = Q K^T (16 x 64 per warp), 3 passes
        float s[8][4] = {};
#pragma unroll
        for (int kc = 0; kc < 4; kc++) {
            uint32_t kb[4][4];
#pragma unroll
            for (int p = 0; p < 4; p++) {
                int row = p * 16 + b_rp;
                int u = (kc * 2 + b_up) ^ (row & 7);
                ldmx4(kb[p], kbase + (uint32_t)(row * 128 + u * 16));
            }
#pragma unroll
            for (int t = 0; t < 8; t++) {
                mma16816(s[t], qah[kc], &kb[t >> 1][(t & 1) * 2]);
                mma16816(s[t], qal[kc], &kb[t >> 1][(t & 1) * 2]);
            }
#pragma unroll
            for (int p = 0; p < 4; p++) {
                int row = p * 16 + b_rp;
                int u = (kc * 2 + b_up) ^ (row & 7);
                ldmx4(kb[p], kbase + 8192 + (uint32_t)(row * 128 + u * 16));
            }
#pragma unroll
            for (int t = 0; t < 8; t++)
                mma16816(s[t], qah[kc], &kb[t >> 1][(t & 1) * 2]);
        }

        // mask + scale
        {
            const int wb = c * 2;
            uint32_t w0[2], w1[2];
            w0[0] = mrow0[wb]; w0[1] = mrow0[wb + 1];
            w1[0] = mrow1[wb]; w1[1] = mrow1[wb + 1];
            uint32_t allm = w0[0] & w0[1] & w1[0] & w1[1];
            if (allm == 0xFFFFFFFFu) {
#pragma unroll
                for (int t = 0; t < 8; t++) {
                    s[t][0] *= 0.125f; s[t][1] *= 0.125f;
                    s[t][2] *= 0.125f; s[t][3] *= 0.125f;
                }
            } else {
#pragma unroll
                for (int t = 0; t < 8; t++) {
                    int c0 = t * 8 + 2 * (lane & 3), c1 = c0 + 1;
                    s[t][0] = ((w0[c0 >> 5] >> (c0 & 31)) & 1) ? s[t][0] * 0.125f : -1e9f;
                    s[t][1] = ((w0[c1 >> 5] >> (c1 & 31)) & 1) ? s[t][1] * 0.125f : -1e9f;
                    s[t][2] = ((w1[c0 >> 5] >> (c0 & 31)) & 1) ? s[t][2] * 0.125f : -1e9f;
                    s[t][3] = ((w1[c1 >> 5] >> (c1 & 31)) & 1) ? s[t][3] * 0.125f : -1e9f;
                }
            }
        }

        // online softmax
        {
            float mx0 = -1e30f, mx1 = -1e30f;
#pragma unroll
            for (int t = 0; t < 8; t++) {
                mx0 = fmaxf(mx0, fmaxf(s[t][0], s[t][1]));
                mx1 = fmaxf(mx1, fmaxf(s[t][2], s[t][3]));
            }
            mx0 = fmaxf(mx0, __shfl_xor_sync(0xffffffffu, mx0, 1));
            mx0 = fmaxf(mx0, __shfl_xor_sync(0xffffffffu, mx0, 2));
            mx1 = fmaxf(mx1, __shfl_xor_sync(0xffffffffu, mx1, 1));
            mx1 = fmaxf(mx1, __shfl_xor_sync(0xffffffffu, mx1, 2));
            float mn0 = fmaxf(m0, mx0), mn1 = fmaxf(m1, mx1);
            float c0f = __expf(m0 - mn0), c1f = __expf(m1 - mn1);
            m0 = mn0; m1 = mn1;
            float ls0 = 0.f, ls1 = 0.f;
#pragma unroll
            for (int t = 0; t < 8; t++) {
                s[t][0] = __expf(s[t][0] - mn0); ls0 += s[t][0];
                s[t][1] = __expf(s[t][1] - mn0); ls0 += s[t][1];
                s[t][2] = __expf(s[t][2] - mn1); ls1 += s[t][2];
                s[t][3] = __expf(s[t][3] - mn1); ls1 += s[t][3];
            }
            l0 = l0 * c0f + ls0; l1 = l1 * c1f + ls1;
#pragma unroll
            for (int t = 0; t < 8; t++) {
                acc[t][0] *= c0f; acc[t][1] *= c0f;
                acc[t][2] *= c1f; acc[t][3] *= c1f;
            }
        }

        // O += P V (register-direct P), 3 passes
#pragma unroll
        for (int kc = 0; kc < 4; kc++) {
            uint32_t pah[4], pal[4];
            pack_hl(s[2 * kc][0],     s[2 * kc][1],     pah[0], pal[0]);
            pack_hl(s[2 * kc][2],     s[2 * kc][3],     pah[1], pal[1]);
            pack_hl(s[2 * kc + 1][0], s[2 * kc + 1][1], pah[2], pal[2]);
            pack_hl(s[2 * kc + 1][2], s[2 * kc + 1][3], pah[3], pal[3]);
            const int vrow = kc * 16 + (((lane >> 3) & 1) << 3) + (lane & 7);
            const int vup = lane >> 4;
#pragma unroll
            for (int g = 0; g < 4; g++) {
                int u = (g * 2 + vup) ^ (vrow & 7);
                uint32_t off = (uint32_t)(vrow * 128 + u * 16);
                uint32_t vb[4];
                ldmx4t(vb, vbase + off);
                mma16816(acc[2 * g],     pah, &vb[0]);
                mma16816(acc[2 * g + 1], pah, &vb[2]);
                mma16816(acc[2 * g],     pal, &vb[0]);
                mma16816(acc[2 * g + 1], pal, &vb[2]);
                ldmx4t(vb, vbase + 8192 + off);
                mma16816(acc[2 * g],     pah, &vb[0]);
                mma16816(acc[2 * g + 1], pah, &vb[2]);
            }
        }
        __syncthreads();
    }

    // finalize -> bf16 hi/lo (feeds O projection)
    l0 += __shfl_xor_sync(0xffffffffu, l0, 1);
    l0 += __shfl_xor_sync(0xffffffffu, l0, 2);
    l1 += __shfl_xor_sync(0xffffffffu, l1, 1);
    l1 += __shfl_xor_sync(0xffffffffu, l1, 2);
    const float inv0 = 1.f / l0, inv1 = 1.f / l1;
    const size_t o0 = ((size_t)(b * SS) + gq0) * DM + h * HD;
    const size_t o1 = ((size_t)(b * SS) + gq1) * DM + h * HD;
#pragma unroll
    for (int t = 0; t < 8; t++) {
        int d = t * 8 + 2 * (lane & 3);
        uint32_t hh, ll;
        pack_hl(acc[t][0] * inv0, acc[t][1] * inv0, hh, ll);
        *(uint32_t*)(g_A_h + o0 + d) = hh;
        *(uint32_t*)(g_A_l + o0 + d) = ll;
        pack_hl(acc[t][2] * inv1, acc[t][3] * inv1, hh, ll);
        *(uint32_t*)(g_A_h + o1 + d) = hh;
        *(uint32_t*)(g_A_l + o1 + d) = ll;
    }
}

static const int GEMM_SMEM = 65536;
static const int ATTN_SMEM = 81920;

extern "C" void kernel_launch(void* const* d_in, const int* in_sizes, int n_in,
                              void* d_out, int out_size)
{
    const float* Xq  = (const float*)d_in[0];
    const float* Xkv = (const float*)d_in[1];
    const int*   msk = (const int*)d_in[2];
    const float* Wq  = (const float*)d_in[3];
    const float* bq  = (const float*)d_in[4];
    const float* Wk  = (const float*)d_in[5];
    const float* bk  = (const float*)d_in[6];
    const float* Wv  = (const float*)d_in[7];
    const float* bv  = (const float*)d_in[8];
    const float* Wo  = (const float*)d_in[9];
    const float* bo  = (const float*)d_in[10];
    float* out = (float*)d_out;

    cudaFuncSetAttribute(gemm_qkv, cudaFuncAttributeMaxDynamicSharedMemorySize, GEMM_SMEM);
    cudaFuncSetAttribute(gemm_o,   cudaFuncAttributeMaxDynamicSharedMemorySize, GEMM_SMEM);
    cudaFuncSetAttribute(attn_tc,  cudaFuncAttributeMaxDynamicSharedMemorySize, ATTN_SMEM);

    const int n4x = NTOK * DM / 4;
    const int n4w = DM * DM / 4;

    split_x<<<dim3(n4x / 256, 2), 256>>>(Xq, Xkv);
    split_w<<<dim3(n4w / 256, 4), 256>>>(Wq, Wk, Wv, Wo);
    mask_pack<<<BB * SS * (SS / 32) / 256, 256>>>(msk);

    gemm_qkv<<<dim3(DM / 128, NTOK / 128, 3), 256, GEMM_SMEM>>>(bq, bk, bv);
    attn_tc<<<dim3(SS / 64, BB * NH), 128, ATTN_SMEM>>>();
    gemm_o<<<dim3(DM / 128, NTOK / 128), 256, GEMM_SMEM>>>(bo, out);
}